// round 1
// baseline (speedup 1.0000x reference)
#include <cuda_runtime.h>

#define NN 512
#define H  64
#define ED 6
#define NL 4
#define LN_EPS 1e-5f

// Scratch (device globals: no allocations allowed)
__device__ float g_h  [NN*H];
__device__ float g_Hd [NN*H];   // dst-side attention projection (+att_b1 folded)
__device__ float g_Hs [NN*H];   // src-side attention projection
__device__ float g_Av [NN*H];   // src-side value projection (+val_b1 folded)
__device__ float g_agg[NN*H];   // pre-val_w2 aggregated values

__device__ __forceinline__ float warp_sum(float v) {
#pragma unroll
    for (int o = 16; o; o >>= 1) v += __shfl_xor_sync(0xffffffffu, v, o);
    return v;
}

// Per-node tables for a layer: Hd = h@Wa[0:64]+b1a, Hs = h@Wa[64:128], Av = h@Wv[0:64]+b1v
__device__ __forceinline__ void compute_tables(
    int d, int t, const float* h_sh,
    const float* __restrict__ attW1, const float* __restrict__ attB1,
    const float* __restrict__ valW1, const float* __restrict__ valB1)
{
    float ad = attB1[t], as = 0.f, av = valB1[t];
#pragma unroll 8
    for (int k = 0; k < H; k++) {
        float hk = h_sh[k];
        ad += hk * attW1[k * H + t];
        as += hk * attW1[(H + k) * H + t];
        av += hk * valW1[k * H + t];
    }
    g_Hd[d * H + t] = ad;
    g_Hs[d * H + t] = as;
    g_Av[d * H + t] = av;
}

// Encoder: h = relu(x@W1+b1)@W2+b2, then layer-0 tables. grid=512, block=64
__global__ void __launch_bounds__(H) enc_kernel(
    const float* __restrict__ x,
    const float* __restrict__ ew1, const float* __restrict__ eb1,
    const float* __restrict__ ew2, const float* __restrict__ eb2,
    const float* __restrict__ attW1, const float* __restrict__ attB1,
    const float* __restrict__ valW1, const float* __restrict__ valB1)
{
    int d = blockIdx.x, t = threadIdx.x;
    __shared__ float xs[ED], hid[H], hsn[H];
    if (t < ED) xs[t] = x[d * ED + t];
    __syncthreads();
    float a = eb1[t];
#pragma unroll
    for (int k = 0; k < ED; k++) a += xs[k] * ew1[k * H + t];
    hid[t] = fmaxf(a, 0.f);
    __syncthreads();
    float hv = eb2[t];
#pragma unroll 8
    for (int k = 0; k < H; k++) hv += hid[k] * ew2[k * H + t];
    g_h[d * H + t] = hv;
    hsn[t] = hv;
    __syncthreads();
    compute_tables(d, t, hsn, attW1, attB1, valW1, valB1);
}

// Edge kernel: one block per dst node d. 256 threads = 8 warps; warp w handles
// src nodes s in [w*64, w*64+64). Phase A: attention logits into a_sh[512].
// Then block softmax. Phase B: agg_pre[d] = sum_s alpha * relu(Av[s] + ea@Wve).
__global__ void __launch_bounds__(256) edge_kernel(
    const float* __restrict__ ea,
    const float* __restrict__ attW1e,   // [6,64] edge rows of att_w1[l]
    const float* __restrict__ attW2,    // [64]
    const float* __restrict__ attB2,    // [1]
    const float* __restrict__ valW1e)   // [6,64] edge rows of val_w1[l]
{
    int d = blockIdx.x;
    int t = threadIdx.x, w = t >> 5, lane = t & 31;
    __shared__ float Hd_sh[H], w2_sh[H];
    __shared__ float Wae[ED * H], Wve[ED * H];
    __shared__ float a_sh[NN];
    __shared__ float part[8 * H];
    __shared__ float red[256];

    if (t < H) { Hd_sh[t] = g_Hd[d * H + t]; w2_sh[t] = attW2[t]; }
    for (int i = t; i < ED * H; i += 256) { Wae[i] = attW1e[i]; Wve[i] = valW1e[i]; }
    __syncthreads();

    const int j0 = lane * 2;
    const float2 hd2 = *(const float2*)(Hd_sh + j0);
    const float2 w22 = *(const float2*)(w2_sh + j0);
    const float b2v = attB2[0];

    // ---- Phase A: attention logits ----
#pragma unroll 2
    for (int i = 0; i < 64; i++) {
        int s = (w << 6) + i;
        const float* ep = ea + (s * NN + d) * ED;
        float eav[ED];
#pragma unroll
        for (int k = 0; k < ED; k++) eav[k] = __ldg(ep + k);
        float2 hs2 = *(const float2*)(g_Hs + s * H + j0);
        float z0 = hd2.x + hs2.x;
        float z1 = hd2.y + hs2.y;
#pragma unroll
        for (int k = 0; k < ED; k++) {
            float2 wv = *(const float2*)(Wae + k * H + j0);
            z0 += eav[k] * wv.x;
            z1 += eav[k] * wv.y;
        }
        z0 = (z0 > 0.f) ? z0 : 0.2f * z0;   // leaky_relu(., 0.2)
        z1 = (z1 > 0.f) ? z1 : 0.2f * z1;
        float p = z0 * w22.x + z1 * w22.y;
        p = warp_sum(p);
        if (lane == 0) a_sh[s] = p + b2v;
    }
    __syncthreads();

    // ---- Block softmax over the 512 logits ----
    float vmax = fmaxf(a_sh[t], a_sh[t + 256]);
    red[t] = vmax;
    __syncthreads();
#pragma unroll
    for (int st = 128; st > 0; st >>= 1) {
        if (t < st) red[t] = fmaxf(red[t], red[t + st]);
        __syncthreads();
    }
    float m = red[0];
    __syncthreads();
    float ex0 = expf(a_sh[t] - m);
    float ex1 = expf(a_sh[t + 256] - m);
    a_sh[t] = ex0;
    a_sh[t + 256] = ex1;
    red[t] = ex0 + ex1;
    __syncthreads();
#pragma unroll
    for (int st = 128; st > 0; st >>= 1) {
        if (t < st) red[t] += red[t + st];
        __syncthreads();
    }
    float inv_s = 1.f / red[0];

    // ---- Phase B: alpha-weighted value aggregation (val_w2 hoisted out) ----
    float acc0 = 0.f, acc1 = 0.f;
#pragma unroll 2
    for (int i = 0; i < 64; i++) {
        int s = (w << 6) + i;
        const float* ep = ea + (s * NN + d) * ED;
        float eav[ED];
#pragma unroll
        for (int k = 0; k < ED; k++) eav[k] = __ldg(ep + k);
        float2 av2 = *(const float2*)(g_Av + s * H + j0);
        float p0 = av2.x, p1 = av2.y;
#pragma unroll
        for (int k = 0; k < ED; k++) {
            float2 wv = *(const float2*)(Wve + k * H + j0);
            p0 += eav[k] * wv.x;
            p1 += eav[k] * wv.y;
        }
        p0 = fmaxf(p0, 0.f);
        p1 = fmaxf(p1, 0.f);
        float al = a_sh[s] * inv_s;
        acc0 += al * p0;
        acc1 += al * p1;
    }
    part[w * H + j0] = acc0;
    part[w * H + j0 + 1] = acc1;
    __syncthreads();
    if (t < H) {
        float sum = 0.f;
#pragma unroll
        for (int ww = 0; ww < 8; ww++) sum += part[ww * H + t];
        g_agg[d * H + t] = sum;
    }
}

// Node kernel: agg = agg_pre@val_w2+b2; u = relu([h,agg]@upd_w1+b)@upd_w2+b2;
// r = u+h; layernorm; then next-layer tables, or decoder if last. grid=512, block=64
__global__ void __launch_bounds__(H) node_kernel(
    const float* __restrict__ valW2, const float* __restrict__ valB2,
    const float* __restrict__ updW1, const float* __restrict__ updB1,
    const float* __restrict__ updW2, const float* __restrict__ updB2,
    const float* __restrict__ lng, const float* __restrict__ lnb,
    const float* __restrict__ nattW1, const float* __restrict__ nattB1,
    const float* __restrict__ nvalW1, const float* __restrict__ nvalB1,
    const float* __restrict__ decW1, const float* __restrict__ decB1,
    const float* __restrict__ decW2, const float* __restrict__ decB2,
    float* __restrict__ out, int last)
{
    int d = blockIdx.x, t = threadIdx.x, lane = t & 31, wid = t >> 5;
    __shared__ float h_sh[H], ag[H], tmp[H], hid[H], hn_sh[H], red[4];
    h_sh[t] = g_h[d * H + t];
    ag[t] = g_agg[d * H + t];
    __syncthreads();

    // agg = agg_pre @ val_w2 + val_b2
    float a2 = valB2[t];
#pragma unroll 8
    for (int k = 0; k < H; k++) a2 += ag[k] * valW2[k * H + t];
    tmp[t] = a2;
    __syncthreads();

    // hidden = relu([h,agg] @ upd_w1 + upd_b1)
    float hd = updB1[t];
#pragma unroll 4
    for (int k = 0; k < H; k++)
        hd += h_sh[k] * updW1[k * H + t] + tmp[k] * updW1[(H + k) * H + t];
    hid[t] = fmaxf(hd, 0.f);
    __syncthreads();

    // u = hidden @ upd_w2 + upd_b2; residual
    float u = updB2[t];
#pragma unroll 8
    for (int k = 0; k < H; k++) u += hid[k] * updW2[k * H + t];
    float r = u + h_sh[t];

    // LayerNorm over H=64 (2 warps)
    float s1 = warp_sum(r);
    if (lane == 0) red[wid] = s1;
    __syncthreads();
    float mu = (red[0] + red[1]) * (1.0f / H);
    float dr = r - mu;
    float s2 = warp_sum(dr * dr);
    __syncthreads();
    if (lane == 0) red[wid] = s2;
    __syncthreads();
    float var = (red[0] + red[1]) * (1.0f / H);
    float hn = lng[t] * dr * rsqrtf(var + LN_EPS) + lnb[t];

    if (!last) {
        g_h[d * H + t] = hn;
        hn_sh[t] = hn;
        __syncthreads();
        compute_tables(d, t, hn_sh, nattW1, nattB1, nvalW1, nvalB1);
    } else {
        hn_sh[t] = hn;
        __syncthreads();
        // decoder: relu(h@dec_w1+b1)@dec_w2+b2 -> scalar
        float dh = decB1[t];
#pragma unroll 8
        for (int k = 0; k < H; k++) dh += hn_sh[k] * decW1[k * H + t];
        dh = fmaxf(dh, 0.f);
        float p = dh * decW2[t];
        float ps = warp_sum(p);
        __syncthreads();
        if (lane == 0) red[wid] = ps;
        __syncthreads();
        if (t == 0) out[d] = red[0] + red[1] + decB2[0];
    }
}

extern "C" void kernel_launch(void* const* d_in, const int* in_sizes, int n_in,
                              void* d_out, int out_size)
{
    const float* x      = (const float*)d_in[0];
    const float* ea     = (const float*)d_in[1];
    const float* enc_w1 = (const float*)d_in[2];
    const float* enc_b1 = (const float*)d_in[3];
    const float* enc_w2 = (const float*)d_in[4];
    const float* enc_b2 = (const float*)d_in[5];
    const float* att_w1 = (const float*)d_in[6];   // [4,134,64]
    const float* att_b1 = (const float*)d_in[7];   // [4,64]
    const float* att_w2 = (const float*)d_in[8];   // [4,64,1]
    const float* att_b2 = (const float*)d_in[9];   // [4,1]
    const float* val_w1 = (const float*)d_in[10];  // [4,70,64]
    const float* val_b1 = (const float*)d_in[11];  // [4,64]
    const float* val_w2 = (const float*)d_in[12];  // [4,64,64]
    const float* val_b2 = (const float*)d_in[13];  // [4,64]
    const float* upd_w1 = (const float*)d_in[14];  // [4,128,64]
    const float* upd_b1 = (const float*)d_in[15];  // [4,64]
    const float* upd_w2 = (const float*)d_in[16];  // [4,64,64]
    const float* upd_b2 = (const float*)d_in[17];  // [4,64]
    const float* ln_g   = (const float*)d_in[18];  // [4,64]
    const float* ln_b   = (const float*)d_in[19];  // [4,64]
    const float* dec_w1 = (const float*)d_in[20];
    const float* dec_b1 = (const float*)d_in[21];
    const float* dec_w2 = (const float*)d_in[22];
    const float* dec_b2 = (const float*)d_in[23];
    // d_in[24] = edge_index: structure is src=e/512, dst=e%512 (exploited directly)

    float* out = (float*)d_out;

    enc_kernel<<<NN, H>>>(x, enc_w1, enc_b1, enc_w2, enc_b2,
                          att_w1, att_b1, val_w1, val_b1);

    for (int l = 0; l < NL; l++) {
        edge_kernel<<<NN, 256>>>(ea,
                                 att_w1 + (l * 134 + 128) * H,
                                 att_w2 + l * H,
                                 att_b2 + l,
                                 val_w1 + (l * 70 + 64) * H);
        int last = (l == NL - 1);
        int nl = (l + 1) % NL;  // dummy-but-valid pointers on last layer
        node_kernel<<<NN, H>>>(val_w2 + l * H * H, val_b2 + l * H,
                               upd_w1 + l * 2 * H * H, upd_b1 + l * H,
                               upd_w2 + l * H * H, upd_b2 + l * H,
                               ln_g + l * H, ln_b + l * H,
                               att_w1 + nl * 134 * H, att_b1 + nl * H,
                               val_w1 + nl * 70 * H, val_b1 + nl * H,
                               dec_w1, dec_b1, dec_w2, dec_b2,
                               out, last);
    }
}

// round 2
// speedup vs baseline: 1.4133x; 1.4133x over previous
#include <cuda_runtime.h>

#define NN 512
#define H  64
#define ED 6
#define NL 4
#define LN_EPS 1e-5f

// Scratch (device globals: no allocations allowed)
__device__ float g_h [NN*H];
__device__ float g_Hd[NN*H];        // dst-side attention projection (+att_b1) — block-private rows
__device__ float g_Hs[2][NN*H];     // src-side attention projection — double buffered (cross-block)
__device__ float g_Av[2][NN*H];     // src-side value projection (+val_b1) — double buffered

__device__ __forceinline__ float warp_sum(float v) {
#pragma unroll
    for (int o = 16; o; o >>= 1) v += __shfl_xor_sync(0xffffffffu, v, o);
    return v;
}
__device__ __forceinline__ float warp_max(float v) {
#pragma unroll
    for (int o = 16; o; o >>= 1) v = fmaxf(v, __shfl_xor_sync(0xffffffffu, v, o));
    return v;
}

// Per-node tables: Hd = h@Wa[0:64]+b1a, Hs = h@Wa[64:128], Av = h@Wv[0:64]+b1v
__device__ __forceinline__ void compute_tables(
    int d, int t, int wb, const float* h_sh,
    const float* __restrict__ attW1, const float* __restrict__ attB1,
    const float* __restrict__ valW1, const float* __restrict__ valB1)
{
    float ad = attB1[t], as = 0.f, av = valB1[t];
#pragma unroll 8
    for (int k = 0; k < H; k++) {
        float hk = h_sh[k];
        ad += hk * attW1[k * H + t];
        as += hk * attW1[(H + k) * H + t];
        av += hk * valW1[k * H + t];
    }
    g_Hd[d * H + t]     = ad;
    g_Hs[wb][d * H + t] = as;
    g_Av[wb][d * H + t] = av;
}

// Encoder: h = relu(x@W1+b1)@W2+b2, then layer-0 tables (buffer 0). grid=512, block=64
__global__ void __launch_bounds__(H) enc_kernel(
    const float* __restrict__ x,
    const float* __restrict__ ew1, const float* __restrict__ eb1,
    const float* __restrict__ ew2, const float* __restrict__ eb2,
    const float* __restrict__ attW1, const float* __restrict__ attB1,
    const float* __restrict__ valW1, const float* __restrict__ valB1)
{
    int d = blockIdx.x, t = threadIdx.x;
    __shared__ float xs[ED], hid[H], hsn[H];
    if (t < ED) xs[t] = x[d * ED + t];
    __syncthreads();
    float a = eb1[t];
#pragma unroll
    for (int k = 0; k < ED; k++) a += xs[k] * ew1[k * H + t];
    hid[t] = fmaxf(a, 0.f);
    __syncthreads();
    float hv = eb2[t];
#pragma unroll 8
    for (int k = 0; k < H; k++) hv += hid[k] * ew2[k * H + t];
    g_h[d * H + t] = hv;
    hsn[t] = hv;
    __syncthreads();
    compute_tables(d, t, 0, hsn, attW1, attB1, valW1, valB1);
}

// Fused layer: one block per dst node d. 512 threads = 16 warps; warp w owns
// src nodes [w*32, w*32+32). Per-warp register softmax, then fused node MLP +
// LayerNorm + next-layer tables (or decoder on the last layer).
__global__ void __launch_bounds__(512, 2) layer_kernel(
    const float* __restrict__ ea,
    const float* __restrict__ attW1e,   // [6,64] edge rows of att_w1[l]
    const float* __restrict__ attW2,    // [64]
    const float* __restrict__ valW1e,   // [6,64] edge rows of val_w1[l]
    const float* __restrict__ valW2, const float* __restrict__ valB2,
    const float* __restrict__ updW1, const float* __restrict__ updB1,
    const float* __restrict__ updW2, const float* __restrict__ updB2,
    const float* __restrict__ lng, const float* __restrict__ lnb,
    const float* __restrict__ nattW1, const float* __restrict__ nattB1,
    const float* __restrict__ nvalW1, const float* __restrict__ nvalB1,
    const float* __restrict__ decW1, const float* __restrict__ decB1,
    const float* __restrict__ decW2, const float* __restrict__ decB2,
    float* __restrict__ out, int rb, int last)
{
    const int d = blockIdx.x;
    const int t = threadIdx.x, w = t >> 5, lane = t & 31;
    const int wb = rb ^ 1;

    __shared__ float pm[16], ps[16], pacc[16 * H];
    __shared__ float agg_sh[H], h_sh[H], tmp_sh[H], hid_sh[H], hn_sh[H], red_sh[4];

    const int j0 = lane * 2;
    const float* HsL = g_Hs[rb];
    const float* AvL = g_Av[rb];

    const float2 hd2 = *(const float2*)(g_Hd + d * H + j0);
    const float2 w22 = *(const float2*)(attW2 + j0);
    float2 wa[ED];
#pragma unroll
    for (int k = 0; k < ED; k++) wa[k] = *(const float2*)(attW1e + k * H + j0);

    const float2* eab = (const float2*)ea;   // ea row = 3 float2 (24B, 8B-aligned)
    const int s0 = w * 32;

    // ---- Pass 1: attention logits, one per lane (att_b2 cancels in softmax) ----
    float my_logit = 0.f;
#pragma unroll 8
    for (int i = 0; i < 32; i++) {
        int s = s0 + i;
        const float2* ep = eab + (size_t)(s * NN + d) * 3;
        float2 e0 = __ldg(ep), e1 = __ldg(ep + 1), e2 = __ldg(ep + 2);
        float2 hs2 = *(const float2*)(HsL + s * H + j0);
        float z0 = hd2.x + hs2.x;
        float z1 = hd2.y + hs2.y;
        z0 += e0.x * wa[0].x; z1 += e0.x * wa[0].y;
        z0 += e0.y * wa[1].x; z1 += e0.y * wa[1].y;
        z0 += e1.x * wa[2].x; z1 += e1.x * wa[2].y;
        z0 += e1.y * wa[3].x; z1 += e1.y * wa[3].y;
        z0 += e2.x * wa[4].x; z1 += e2.x * wa[4].y;
        z0 += e2.y * wa[5].x; z1 += e2.y * wa[5].y;
        z0 = fmaxf(z0, 0.2f * z0);            // leaky_relu(., 0.2)
        z1 = fmaxf(z1, 0.2f * z1);
        float p = z0 * w22.x + z1 * w22.y;
        p = warp_sum(p);
        if (lane == i) my_logit = p;
    }

    // ---- Per-warp softmax (register resident): one exp per edge total ----
    float m = warp_max(my_logit);
    float eexp = __expf(my_logit - m);
    float s_w = warp_sum(eexp);

    // ---- Pass 2: alpha-weighted value aggregation (val_w2 hoisted out) ----
    float2 wv[ED];
#pragma unroll
    for (int k = 0; k < ED; k++) wv[k] = *(const float2*)(valW1e + k * H + j0);

    float acc0 = 0.f, acc1 = 0.f;
#pragma unroll 8
    for (int i = 0; i < 32; i++) {
        int s = s0 + i;
        const float2* ep = eab + (size_t)(s * NN + d) * 3;
        float2 e0 = __ldg(ep), e1 = __ldg(ep + 1), e2 = __ldg(ep + 2);
        float2 av2 = *(const float2*)(AvL + s * H + j0);
        float p0 = av2.x, p1 = av2.y;
        p0 += e0.x * wv[0].x; p1 += e0.x * wv[0].y;
        p0 += e0.y * wv[1].x; p1 += e0.y * wv[1].y;
        p0 += e1.x * wv[2].x; p1 += e1.x * wv[2].y;
        p0 += e1.y * wv[3].x; p1 += e1.y * wv[3].y;
        p0 += e2.x * wv[4].x; p1 += e2.x * wv[4].y;
        p0 += e2.y * wv[5].x; p1 += e2.y * wv[5].y;
        p0 = fmaxf(p0, 0.f);
        p1 = fmaxf(p1, 0.f);
        float wgt = __shfl_sync(0xffffffffu, eexp, i);
        acc0 += wgt * p0;
        acc1 += wgt * p1;
    }
    if (lane == 0) { pm[w] = m; ps[w] = s_w; }
    pacc[w * H + j0]     = acc0;
    pacc[w * H + j0 + 1] = acc1;
    __syncthreads();

    // ---- Combine 16 warp partials + start node phase (threads 0..63) ----
    if (t < H) {
        float M = pm[0];
#pragma unroll
        for (int k = 1; k < 16; k++) M = fmaxf(M, pm[k]);
        float stot = 0.f, acc = 0.f;
#pragma unroll
        for (int k = 0; k < 16; k++) {
            float sc = __expf(pm[k] - M);
            stot += ps[k] * sc;
            acc  += pacc[k * H + t] * sc;
        }
        agg_sh[t] = acc / stot;
        h_sh[t]   = g_h[d * H + t];
    }
    __syncthreads();

    // agg = agg_pre @ val_w2 + val_b2
    if (t < H) {
        float a2 = valB2[t];
#pragma unroll 8
        for (int k = 0; k < H; k++) a2 += agg_sh[k] * valW2[k * H + t];
        tmp_sh[t] = a2;
    }
    __syncthreads();

    // hidden = relu([h,agg] @ upd_w1 + upd_b1)
    if (t < H) {
        float hd = updB1[t];
#pragma unroll 4
        for (int k = 0; k < H; k++)
            hd += h_sh[k] * updW1[k * H + t] + tmp_sh[k] * updW1[(H + k) * H + t];
        hid_sh[t] = fmaxf(hd, 0.f);
    }
    __syncthreads();

    // u = hidden @ upd_w2 + upd_b2; residual; LayerNorm (threads 0..63 = warps 0,1)
    float r = 0.f, mu = 0.f, dr = 0.f;
    if (t < H) {
        float u = updB2[t];
#pragma unroll 8
        for (int k = 0; k < H; k++) u += hid_sh[k] * updW2[k * H + t];
        r = u + h_sh[t];
        float s1 = warp_sum(r);
        if (lane == 0) red_sh[w] = s1;
    }
    __syncthreads();
    if (t < H) {
        mu = (red_sh[0] + red_sh[1]) * (1.0f / H);
        dr = r - mu;
        float s2 = warp_sum(dr * dr);
        if (lane == 0) red_sh[w + 2] = s2;
    }
    __syncthreads();
    if (t < H) {
        float var = (red_sh[2] + red_sh[3]) * (1.0f / H);
        float hn = lng[t] * dr * rsqrtf(var + LN_EPS) + lnb[t];
        hn_sh[t] = hn;
        if (!last) g_h[d * H + t] = hn;
    }
    __syncthreads();

    if (!last) {
        if (t < H)
            compute_tables(d, t, wb, hn_sh, nattW1, nattB1, nvalW1, nvalB1);
    } else {
        // decoder: relu(h@dec_w1+b1)@dec_w2+b2 -> scalar
        if (t < H) {
            float dh = decB1[t];
#pragma unroll 8
            for (int k = 0; k < H; k++) dh += hn_sh[k] * decW1[k * H + t];
            dh = fmaxf(dh, 0.f);
            float p = dh * decW2[t];
            float psum = warp_sum(p);
            if (lane == 0) red_sh[w] = psum;
        }
        __syncthreads();
        if (t == 0) out[d] = red_sh[0] + red_sh[1] + decB2[0];
    }
}

extern "C" void kernel_launch(void* const* d_in, const int* in_sizes, int n_in,
                              void* d_out, int out_size)
{
    const float* x      = (const float*)d_in[0];
    const float* ea     = (const float*)d_in[1];
    const float* enc_w1 = (const float*)d_in[2];
    const float* enc_b1 = (const float*)d_in[3];
    const float* enc_w2 = (const float*)d_in[4];
    const float* enc_b2 = (const float*)d_in[5];
    const float* att_w1 = (const float*)d_in[6];   // [4,134,64]
    const float* att_b1 = (const float*)d_in[7];   // [4,64]
    const float* att_w2 = (const float*)d_in[8];   // [4,64,1]
    // d_in[9] = att_b2 — cancels inside softmax, unused
    const float* val_w1 = (const float*)d_in[10];  // [4,70,64]
    const float* val_b1 = (const float*)d_in[11];  // [4,64]
    const float* val_w2 = (const float*)d_in[12];  // [4,64,64]
    const float* val_b2 = (const float*)d_in[13];  // [4,64]
    const float* upd_w1 = (const float*)d_in[14];  // [4,128,64]
    const float* upd_b1 = (const float*)d_in[15];  // [4,64]
    const float* upd_w2 = (const float*)d_in[16];  // [4,64,64]
    const float* upd_b2 = (const float*)d_in[17];  // [4,64]
    const float* ln_g   = (const float*)d_in[18];  // [4,64]
    const float* ln_b   = (const float*)d_in[19];  // [4,64]
    const float* dec_w1 = (const float*)d_in[20];
    const float* dec_b1 = (const float*)d_in[21];
    const float* dec_w2 = (const float*)d_in[22];
    const float* dec_b2 = (const float*)d_in[23];
    // d_in[24] = edge_index: structure is src=e/512, dst=e%512 (exploited directly)

    float* out = (float*)d_out;

    enc_kernel<<<NN, H>>>(x, enc_w1, enc_b1, enc_w2, enc_b2,
                          att_w1, att_b1, val_w1, val_b1);

    for (int l = 0; l < NL; l++) {
        int last = (l == NL - 1);
        int nl = (l + 1) % NL;      // dummy-but-valid pointers on last layer
        int rb = l & 1;             // enc wrote buffer 0; layer l reads l&1, writes (l&1)^1
        layer_kernel<<<NN, 512>>>(ea,
                                  att_w1 + (l * 134 + 128) * H,
                                  att_w2 + l * H,
                                  val_w1 + (l * 70 + 64) * H,
                                  val_w2 + l * H * H, val_b2 + l * H,
                                  upd_w1 + l * 2 * H * H, upd_b1 + l * H,
                                  upd_w2 + l * H * H, upd_b2 + l * H,
                                  ln_g + l * H, ln_b + l * H,
                                  att_w1 + nl * 134 * H, att_b1 + nl * H,
                                  val_w1 + nl * 70 * H, val_b1 + nl * H,
                                  dec_w1, dec_b1, dec_w2, dec_b2,
                                  out, rb, last);
    }
}

// round 3
// speedup vs baseline: 2.1026x; 1.4878x over previous
#include <cuda_runtime.h>
#include <string.h>

#define NN 512
#define H  64
#define ED 6
#define NL 4
#define EE (NN*NN)
#define LN_EPS 1e-5f

// Scratch (device globals: no allocations allowed)
__device__ float g_h  [NN*H];
__device__ float g_Hd [NN*H];         // dst-side attention proj (+att_b1), row-major (block-private rows)
__device__ float g_HsT[2][H*NN];      // src-side attention proj, DIM-MAJOR [j][s], double buffered
__device__ float g_Av [2][NN*H];      // src-side value proj (+val_b1), row-major, double buffered
__device__ float g_eaT[ED*EE];        // edge_attr transposed: eaT[k][d][s]

__device__ __forceinline__ float warp_sum(float v) {
#pragma unroll
    for (int o = 16; o; o >>= 1) v += __shfl_xor_sync(0xffffffffu, v, o);
    return v;
}
__device__ __forceinline__ float warp_max(float v) {
#pragma unroll
    for (int o = 16; o; o >>= 1) v = fmaxf(v, __shfl_xor_sync(0xffffffffu, v, o));
    return v;
}

// Packed fp32x2 ops (sm_103a): 2 FMAs per instruction
__device__ __forceinline__ float2 ffma2(float2 a, float2 b, float2 c) {
    unsigned long long ua, ub, uc, ur;
    memcpy(&ua, &a, 8); memcpy(&ub, &b, 8); memcpy(&uc, &c, 8);
    asm("fma.rn.f32x2 %0, %1, %2, %3;" : "=l"(ur) : "l"(ua), "l"(ub), "l"(uc));
    float2 r; memcpy(&r, &ur, 8); return r;
}
__device__ __forceinline__ float2 fadd2(float2 a, float2 b) {
    unsigned long long ua, ub, ur;
    memcpy(&ua, &a, 8); memcpy(&ub, &b, 8);
    asm("add.rn.f32x2 %0, %1, %2;" : "=l"(ur) : "l"(ua), "l"(ub));
    float2 r; memcpy(&r, &ur, 8); return r;
}

// Per-node tables: Hd = h@Wa[0:64]+b1a (row), HsT = h@Wa[64:128] (dim-major), Av = h@Wv[0:64]+b1v (row)
__device__ __forceinline__ void compute_tables(
    int d, int t, int wb, const float* h_sh,
    const float* __restrict__ attW1, const float* __restrict__ attB1,
    const float* __restrict__ valW1, const float* __restrict__ valB1)
{
    float ad = attB1[t], as = 0.f, av = valB1[t];
#pragma unroll 8
    for (int k = 0; k < H; k++) {
        float hk = h_sh[k];
        ad += hk * attW1[k * H + t];
        as += hk * attW1[(H + k) * H + t];
        av += hk * valW1[k * H + t];
    }
    g_Hd[d * H + t]          = ad;
    g_HsT[wb][t * NN + d]    = as;     // transposed
    g_Av[wb][d * H + t]      = av;
}

// Transpose edge_attr: ea[s][d][k] -> eaT[k][d][s]. grid (16,16), block 256.
__global__ void __launch_bounds__(256) ea_transpose_kernel(const float* __restrict__ ea)
{
    __shared__ float t_sh[ED][32][33];
    const int t = threadIdx.x, w = t >> 5, lane = t & 31;
    const int bs = blockIdx.x * 32, bd = blockIdx.y * 32;

#pragma unroll
    for (int rr = 0; rr < 4; rr++) {
        int s_loc = w + rr * 8;
        const float* base = ea + ((size_t)(bs + s_loc) * NN + bd) * ED + lane * ED;
        float2 v0 = *(const float2*)(base);
        float2 v1 = *(const float2*)(base + 2);
        float2 v2 = *(const float2*)(base + 4);
        t_sh[0][lane][s_loc] = v0.x; t_sh[1][lane][s_loc] = v0.y;
        t_sh[2][lane][s_loc] = v1.x; t_sh[3][lane][s_loc] = v1.y;
        t_sh[4][lane][s_loc] = v2.x; t_sh[5][lane][s_loc] = v2.y;
    }
    __syncthreads();
#pragma unroll
    for (int idx = t; idx < ED * 32 * 32; idx += 256) {
        int k = idx >> 10, r = idx & 1023, dl = r >> 5, sl = r & 31;
        g_eaT[(size_t)k * EE + (size_t)(bd + dl) * NN + bs + sl] = t_sh[k][dl][sl];
    }
}

// Encoder: h = relu(x@W1+b1)@W2+b2, then layer-0 tables (buffer 0). grid=512, block=64
__global__ void __launch_bounds__(H) enc_kernel(
    const float* __restrict__ x,
    const float* __restrict__ ew1, const float* __restrict__ eb1,
    const float* __restrict__ ew2, const float* __restrict__ eb2,
    const float* __restrict__ attW1, const float* __restrict__ attB1,
    const float* __restrict__ valW1, const float* __restrict__ valB1)
{
    int d = blockIdx.x, t = threadIdx.x;
    __shared__ float xs[ED], hid[H], hsn[H];
    if (t < ED) xs[t] = x[d * ED + t];
    __syncthreads();
    float a = eb1[t];
#pragma unroll
    for (int k = 0; k < ED; k++) a += xs[k] * ew1[k * H + t];
    hid[t] = fmaxf(a, 0.f);
    __syncthreads();
    float hv = eb2[t];
#pragma unroll 8
    for (int k = 0; k < H; k++) hv += hid[k] * ew2[k * H + t];
    g_h[d * H + t] = hv;
    hsn[t] = hv;
    __syncthreads();
    compute_tables(d, t, 0, hsn, attW1, attB1, valW1, valB1);
}

// Fused layer: one block per dst node d. 256 threads = 8 warps. Warp w owns src
// nodes [w*64, w*64+64); lane owns the pair (w*64+2*lane, +1). Pass 1 computes
// both logits with an independent FMA2 stream (no per-edge reductions); per-warp
// register softmax; pass 2 (lane owns dim pair) aggregates values; node MLP +
// LayerNorm + next-layer tables (or decoder) fused at the end.
__global__ void __launch_bounds__(256, 4) layer_kernel(
    const float* __restrict__ attW1e,   // [6,64] edge rows of att_w1[l]
    const float* __restrict__ attW2,    // [64]
    const float* __restrict__ valW1e,   // [6,64] edge rows of val_w1[l]
    const float* __restrict__ valW2, const float* __restrict__ valB2,
    const float* __restrict__ updW1, const float* __restrict__ updB1,
    const float* __restrict__ updW2, const float* __restrict__ updB2,
    const float* __restrict__ lng, const float* __restrict__ lnb,
    const float* __restrict__ nattW1, const float* __restrict__ nattB1,
    const float* __restrict__ nvalW1, const float* __restrict__ nvalB1,
    const float* __restrict__ decW1, const float* __restrict__ decB1,
    const float* __restrict__ decW2, const float* __restrict__ decB2,
    float* __restrict__ out, int rb, int last)
{
    const int d = blockIdx.x;
    const int t = threadIdx.x, w = t >> 5, lane = t & 31;
    const int wb = rb ^ 1;

    __shared__ float2 waT2[H * 8];      // [j][8]: wa0..wa5, w2, hd — each value duplicated
    __shared__ float2 ea_sh[3 * NN];    // [c][s]: (ea_{2c}(s), ea_{2c+1}(s))
    __shared__ float pm[8], ps[8], pacc[8 * H];
    __shared__ float part4[4 * H];
    __shared__ float agg_sh[H], h_sh[H], tmp_sh[H], hid_sh[H], hn_sh[H], red_sh[4];

    // Prologue: attention weight table (duplicated for f32x2) + Hd row
    if (t < H) {
        int j = t;
#pragma unroll
        for (int k = 0; k < ED; k++) {
            float v = attW1e[k * H + j];
            waT2[j * 8 + k] = make_float2(v, v);
        }
        float w2v = attW2[j];
        waT2[j * 8 + 6] = make_float2(w2v, w2v);
        float hdv = g_Hd[d * H + j];
        waT2[j * 8 + 7] = make_float2(hdv, hdv);
    }

    const float* HsT = g_HsT[rb];
    const float* AvL = g_Av[rb];
    const int sa = w * 64 + 2 * lane;   // src pair (sa, sa+1)

    // Load ea for my two srcs (coalesced from eaT) and stash for pass 2
    float2 eav[ED];
#pragma unroll
    for (int k = 0; k < ED; k++)
        eav[k] = *(const float2*)(g_eaT + (size_t)k * EE + d * NN + sa);
#pragma unroll
    for (int c = 0; c < 3; c++) {
        float4 v4 = make_float4(eav[2 * c].x, eav[2 * c + 1].x,
                                eav[2 * c].y, eav[2 * c + 1].y);
        *(float4*)(ea_sh + c * NN + sa) = v4;
    }
    __syncthreads();

    // ---- Pass 1: attention logits, 2 edges per lane, pure FMA2 stream ----
    float2 lg = make_float2(0.f, 0.f);
    const float* hsrow = HsT + sa;
#pragma unroll 8
    for (int j = 0; j < H; j++) {
        float4 a0 = *(const float4*)(waT2 + j * 8);       // (wa0,wa0,wa1,wa1)
        float4 a1 = *(const float4*)(waT2 + j * 8 + 2);   // (wa2,wa2,wa3,wa3)
        float4 a2 = *(const float4*)(waT2 + j * 8 + 4);   // (wa4,wa4,wa5,wa5)
        float4 a3 = *(const float4*)(waT2 + j * 8 + 6);   // (w2, w2, hd, hd)
        float2 hs2 = *(const float2*)(hsrow + j * NN);
        float2 z = fadd2(hs2, make_float2(a3.z, a3.w));
        z = ffma2(eav[0], make_float2(a0.x, a0.y), z);
        z = ffma2(eav[1], make_float2(a0.z, a0.w), z);
        z = ffma2(eav[2], make_float2(a1.x, a1.y), z);
        z = ffma2(eav[3], make_float2(a1.z, a1.w), z);
        z = ffma2(eav[4], make_float2(a2.x, a2.y), z);
        z = ffma2(eav[5], make_float2(a2.z, a2.w), z);
        z.x = fmaxf(z.x, 0.2f * z.x);   // leaky_relu(., 0.2)
        z.y = fmaxf(z.y, 0.2f * z.y);
        lg = ffma2(z, make_float2(a3.x, a3.y), lg);
    }

    // ---- Per-warp register softmax over 64 edges ----
    float m = warp_max(fmaxf(lg.x, lg.y));
    float e1 = __expf(lg.x - m);
    float e2 = __expf(lg.y - m);
    float s_w = warp_sum(e1 + e2);
    if (lane == 0) { pm[w] = m; ps[w] = s_w; }

    // ---- Pass 2: alpha-weighted value aggregation (lane owns dim pair) ----
    const int j0 = 2 * lane;
    float2 wv[ED];
#pragma unroll
    for (int k = 0; k < ED; k++) wv[k] = *(const float2*)(valW1e + k * H + j0);

    float2 acc = make_float2(0.f, 0.f);
    const int s0 = w * 64;
#pragma unroll 4
    for (int i = 0; i < 64; i++) {
        int s = s0 + i;
        float2 e01 = ea_sh[0 * NN + s];
        float2 e23 = ea_sh[1 * NN + s];
        float2 e45 = ea_sh[2 * NN + s];
        float2 p = *(const float2*)(AvL + s * H + j0);
        p.x += e01.x * wv[0].x; p.y += e01.x * wv[0].y;
        p.x += e01.y * wv[1].x; p.y += e01.y * wv[1].y;
        p.x += e23.x * wv[2].x; p.y += e23.x * wv[2].y;
        p.x += e23.y * wv[3].x; p.y += e23.y * wv[3].y;
        p.x += e45.x * wv[4].x; p.y += e45.x * wv[4].y;
        p.x += e45.y * wv[5].x; p.y += e45.y * wv[5].y;
        p.x = fmaxf(p.x, 0.f);
        p.y = fmaxf(p.y, 0.f);
        float wgt = __shfl_sync(0xffffffffu, (i & 1) ? e2 : e1, i >> 1);
        acc.x += wgt * p.x;
        acc.y += wgt * p.y;
    }
    *(float2*)(pacc + w * H + j0) = acc;
    __syncthreads();

    // ---- Combine 8 warp softmax partials (threads 0..63) ----
    if (t < H) {
        float M = pm[0];
#pragma unroll
        for (int k = 1; k < 8; k++) M = fmaxf(M, pm[k]);
        float stot = 0.f, a = 0.f;
#pragma unroll
        for (int k = 0; k < 8; k++) {
            float sc = __expf(pm[k] - M);
            stot += ps[k] * sc;
            a    += pacc[k * H + t] * sc;
        }
        agg_sh[t] = a / stot;
        h_sh[t]   = g_h[d * H + t];
    }
    __syncthreads();

    // ---- Node phase, 4-way k-split matvecs over all 256 threads ----
    const int o = t & 63, q = t >> 6;

    // stage 1: tmp = val_b2 + agg @ val_w2
    {
        float p = 0.f;
        int k0 = q * 16;
#pragma unroll
        for (int kk = 0; kk < 16; kk++) p += agg_sh[k0 + kk] * valW2[(k0 + kk) * H + o];
        part4[q * H + o] = p;
    }
    __syncthreads();
    if (t < H) tmp_sh[t] = valB2[t] + part4[t] + part4[H + t] + part4[2 * H + t] + part4[3 * H + t];
    __syncthreads();

    // stage 2: hid = relu(upd_b1 + [h,tmp] @ upd_w1)
    {
        const float* srcv = (q < 2) ? h_sh : tmp_sh;
        int koff = (q & 1) * 32;
        int rbase = ((q >= 2) ? H : 0) + koff;
        float p = 0.f;
#pragma unroll
        for (int kk = 0; kk < 32; kk++) p += srcv[koff + kk] * updW1[(rbase + kk) * H + o];
        part4[q * H + o] = p;
    }
    __syncthreads();
    if (t < H) hid_sh[t] = fmaxf(updB1[t] + part4[t] + part4[H + t] + part4[2 * H + t] + part4[3 * H + t], 0.f);
    __syncthreads();

    // stage 3: u = upd_b2 + hid @ upd_w2
    {
        float p = 0.f;
        int k0 = q * 16;
#pragma unroll
        for (int kk = 0; kk < 16; kk++) p += hid_sh[k0 + kk] * updW2[(k0 + kk) * H + o];
        part4[q * H + o] = p;
    }
    __syncthreads();

    // residual + LayerNorm (threads 0..63 = warps 0,1)
    float r = 0.f, dr = 0.f;
    if (t < H) {
        float u = updB2[t] + part4[t] + part4[H + t] + part4[2 * H + t] + part4[3 * H + t];
        r = u + h_sh[t];
        float s1 = warp_sum(r);
        if (lane == 0) red_sh[w] = s1;
    }
    __syncthreads();
    if (t < H) {
        float mu = (red_sh[0] + red_sh[1]) * (1.0f / H);
        dr = r - mu;
        float s2 = warp_sum(dr * dr);
        if (lane == 0) red_sh[w + 2] = s2;
    }
    __syncthreads();
    if (t < H) {
        float var = (red_sh[2] + red_sh[3]) * (1.0f / H);
        float hn = lng[t] * dr * rsqrtf(var + LN_EPS) + lnb[t];
        hn_sh[t] = hn;
        if (!last) g_h[d * H + t] = hn;
    }
    __syncthreads();

    if (!last) {
        if (t < H)
            compute_tables(d, t, wb, hn_sh, nattW1, nattB1, nvalW1, nvalB1);
    } else {
        if (t < H) {
            float dh = decB1[t];
#pragma unroll 8
            for (int k = 0; k < H; k++) dh += hn_sh[k] * decW1[k * H + t];
            dh = fmaxf(dh, 0.f);
            float p = dh * decW2[t];
            float psum = warp_sum(p);
            if (lane == 0) red_sh[w] = psum;
        }
        __syncthreads();
        if (t == 0) out[d] = red_sh[0] + red_sh[1] + decB2[0];
    }
}

extern "C" void kernel_launch(void* const* d_in, const int* in_sizes, int n_in,
                              void* d_out, int out_size)
{
    const float* x      = (const float*)d_in[0];
    const float* ea     = (const float*)d_in[1];
    const float* enc_w1 = (const float*)d_in[2];
    const float* enc_b1 = (const float*)d_in[3];
    const float* enc_w2 = (const float*)d_in[4];
    const float* enc_b2 = (const float*)d_in[5];
    const float* att_w1 = (const float*)d_in[6];   // [4,134,64]
    const float* att_b1 = (const float*)d_in[7];   // [4,64]
    const float* att_w2 = (const float*)d_in[8];   // [4,64,1]
    // d_in[9] = att_b2 — cancels inside softmax, unused
    const float* val_w1 = (const float*)d_in[10];  // [4,70,64]
    const float* val_b1 = (const float*)d_in[11];  // [4,64]
    const float* val_w2 = (const float*)d_in[12];  // [4,64,64]
    const float* val_b2 = (const float*)d_in[13];  // [4,64]
    const float* upd_w1 = (const float*)d_in[14];  // [4,128,64]
    const float* upd_b1 = (const float*)d_in[15];  // [4,64]
    const float* upd_w2 = (const float*)d_in[16];  // [4,64,64]
    const float* upd_b2 = (const float*)d_in[17];  // [4,64]
    const float* ln_g   = (const float*)d_in[18];  // [4,64]
    const float* ln_b   = (const float*)d_in[19];  // [4,64]
    const float* dec_w1 = (const float*)d_in[20];
    const float* dec_b1 = (const float*)d_in[21];
    const float* dec_w2 = (const float*)d_in[22];
    const float* dec_b2 = (const float*)d_in[23];
    // d_in[24] = edge_index: src=e/512, dst=e%512 (structure exploited directly)

    float* out = (float*)d_out;

    ea_transpose_kernel<<<dim3(16, 16), 256>>>(ea);
    enc_kernel<<<NN, H>>>(x, enc_w1, enc_b1, enc_w2, enc_b2,
                          att_w1, att_b1, val_w1, val_b1);

    for (int l = 0; l < NL; l++) {
        int last = (l == NL - 1);
        int nl = (l + 1) % NL;      // dummy-but-valid pointers on last layer
        int rb = l & 1;             // enc wrote buffer 0; layer l reads l&1, writes (l&1)^1
        layer_kernel<<<NN, 256>>>(att_w1 + (l * 134 + 128) * H,
                                  att_w2 + l * H,
                                  val_w1 + (l * 70 + 64) * H,
                                  val_w2 + l * H * H, val_b2 + l * H,
                                  upd_w1 + l * 2 * H * H, upd_b1 + l * H,
                                  upd_w2 + l * H * H, upd_b2 + l * H,
                                  ln_g + l * H, ln_b + l * H,
                                  att_w1 + nl * 134 * H, att_b1 + nl * H,
                                  val_w1 + nl * 70 * H, val_b1 + nl * H,
                                  dec_w1, dec_b1, dec_w2, dec_b2,
                                  out, rb, last);
    }
}

// round 4
// speedup vs baseline: 2.2429x; 1.0667x over previous
#include <cuda_runtime.h>
#include <string.h>

#define NN 512
#define H  64
#define ED 6
#define NL 4
#define EE (NN*NN)
#define LN_EPS 1e-5f

// Scratch (device globals: no allocations allowed)
__device__ float g_h  [NN*H];
__device__ float g_Hd [NN*H];         // dst-side attention proj (+att_b1), row-major
__device__ float g_HsT[2][H*NN];      // src-side attention proj, DIM-MAJOR [j][s], double buffered
__device__ float g_Av [2][NN*H];      // src-side value proj (+val_b1), row-major, double buffered
__device__ float g_eaT[ED*EE];        // edge_attr transposed: eaT[k][d][s]

__device__ __forceinline__ float warp_sum(float v) {
#pragma unroll
    for (int o = 16; o; o >>= 1) v += __shfl_xor_sync(0xffffffffu, v, o);
    return v;
}
__device__ __forceinline__ float warp_max(float v) {
#pragma unroll
    for (int o = 16; o; o >>= 1) v = fmaxf(v, __shfl_xor_sync(0xffffffffu, v, o));
    return v;
}

// Packed fp32x2 ops (sm_103a): 2 fp32 FMAs per instruction
__device__ __forceinline__ float2 ffma2(float2 a, float2 b, float2 c) {
    unsigned long long ua, ub, uc, ur;
    memcpy(&ua, &a, 8); memcpy(&ub, &b, 8); memcpy(&uc, &c, 8);
    asm("fma.rn.f32x2 %0, %1, %2, %3;" : "=l"(ur) : "l"(ua), "l"(ub), "l"(uc));
    float2 r; memcpy(&r, &ur, 8); return r;
}
__device__ __forceinline__ float2 fadd2(float2 a, float2 b) {
    unsigned long long ua, ub, ur;
    memcpy(&ua, &a, 8); memcpy(&ub, &b, 8);
    asm("add.rn.f32x2 %0, %1, %2;" : "=l"(ur) : "l"(ua), "l"(ub));
    float2 r; memcpy(&r, &ur, 8); return r;
}
__device__ __forceinline__ float2 fmul2(float2 a, float2 b) {
    unsigned long long ua, ub, ur;
    memcpy(&ua, &a, 8); memcpy(&ub, &b, 8);
    asm("mul.rn.f32x2 %0, %1, %2;" : "=l"(ur) : "l"(ua), "l"(ub));
    float2 r; memcpy(&r, &ur, 8); return r;
}

// Per-node tables: Hd = h@Wa[0:64]+b1a (row), HsT = h@Wa[64:128] (dim-major), Av = h@Wv[0:64]+b1v (row)
__device__ __forceinline__ void compute_tables(
    int d, int t, int wb, const float* h_sh,
    const float* __restrict__ attW1, const float* __restrict__ attB1,
    const float* __restrict__ valW1, const float* __restrict__ valB1)
{
    float ad = attB1[t], as = 0.f, av = valB1[t];
#pragma unroll 8
    for (int k = 0; k < H; k++) {
        float hk = h_sh[k];
        ad += hk * attW1[k * H + t];
        as += hk * attW1[(H + k) * H + t];
        av += hk * valW1[k * H + t];
    }
    g_Hd[d * H + t]       = ad;
    g_HsT[wb][t * NN + d] = as;
    g_Av[wb][d * H + t]   = av;
}

// Transpose edge_attr: ea[s][d][k] -> eaT[k][d][s]. grid (16,16), block 256.
__global__ void __launch_bounds__(256) ea_transpose_kernel(const float* __restrict__ ea)
{
    __shared__ float t_sh[ED][32][33];
    const int t = threadIdx.x, w = t >> 5, lane = t & 31;
    const int bs = blockIdx.x * 32, bd = blockIdx.y * 32;

#pragma unroll
    for (int rr = 0; rr < 4; rr++) {
        int s_loc = w + rr * 8;
        const float* base = ea + ((size_t)(bs + s_loc) * NN + bd) * ED + lane * ED;
        float2 v0 = *(const float2*)(base);
        float2 v1 = *(const float2*)(base + 2);
        float2 v2 = *(const float2*)(base + 4);
        t_sh[0][lane][s_loc] = v0.x; t_sh[1][lane][s_loc] = v0.y;
        t_sh[2][lane][s_loc] = v1.x; t_sh[3][lane][s_loc] = v1.y;
        t_sh[4][lane][s_loc] = v2.x; t_sh[5][lane][s_loc] = v2.y;
    }
    __syncthreads();
#pragma unroll
    for (int idx = t; idx < ED * 32 * 32; idx += 256) {
        int k = idx >> 10, r = idx & 1023, dl = r >> 5, sl = r & 31;
        g_eaT[(size_t)k * EE + (size_t)(bd + dl) * NN + bs + sl] = t_sh[k][dl][sl];
    }
}

// Encoder: h = relu(x@W1+b1)@W2+b2, then layer-0 tables (buffer 0). grid=512, block=64
__global__ void __launch_bounds__(H) enc_kernel(
    const float* __restrict__ x,
    const float* __restrict__ ew1, const float* __restrict__ eb1,
    const float* __restrict__ ew2, const float* __restrict__ eb2,
    const float* __restrict__ attW1, const float* __restrict__ attB1,
    const float* __restrict__ valW1, const float* __restrict__ valB1)
{
    int d = blockIdx.x, t = threadIdx.x;
    __shared__ float xs[ED], hid[H], hsn[H];
    if (t < ED) xs[t] = x[d * ED + t];
    __syncthreads();
    float a = eb1[t];
#pragma unroll
    for (int k = 0; k < ED; k++) a += xs[k] * ew1[k * H + t];
    hid[t] = fmaxf(a, 0.f);
    __syncthreads();
    float hv = eb2[t];
#pragma unroll 8
    for (int k = 0; k < H; k++) hv += hid[k] * ew2[k * H + t];
    g_h[d * H + t] = hv;
    hsn[t] = hv;
    __syncthreads();
    compute_tables(d, t, 0, hsn, attW1, attB1, valW1, valB1);
}

// Fused layer: one block per dst node d. 256 threads = 8 warps.
// Pass 1 (j-split): warps 0-3 own srcs [wg*128, wg*128+128) with j in [0,32);
// warps 4-7 same srcs, j in [32,64). Lane owns 4 srcs (two f32x2 pairs).
// Partial logits exchanged through smem; warps 0-3 do register softmax.
// Pass 2: warp w owns srcs [w*64, w*64+64), dims (2*lane, 2*lane+1), f32x2 math
// with duplicated ea pairs from smem. Node MLP + LN + next tables fused.
__global__ void __launch_bounds__(256, 4) layer_kernel(
    const float* __restrict__ attW1e,   // [6,64] edge rows of att_w1[l]
    const float* __restrict__ attW2,    // [64]
    const float* __restrict__ valW1e,   // [6,64] edge rows of val_w1[l]
    const float* __restrict__ valW2, const float* __restrict__ valB2,
    const float* __restrict__ updW1, const float* __restrict__ updB1,
    const float* __restrict__ updW2, const float* __restrict__ updB2,
    const float* __restrict__ lng, const float* __restrict__ lnb,
    const float* __restrict__ nattW1, const float* __restrict__ nattB1,
    const float* __restrict__ nvalW1, const float* __restrict__ nvalB1,
    const float* __restrict__ decW1, const float* __restrict__ decB1,
    const float* __restrict__ decW2, const float* __restrict__ decB2,
    float* __restrict__ out, int rb, int last)
{
    const int d = blockIdx.x;
    const int t = threadIdx.x, w = t >> 5, lane = t & 31;
    const int wg = w & 3;            // src group
    const int jbase = (w >> 2) * 32; // j half
    const int wb = rb ^ 1;

    __shared__ float4 wa4[H * 4];    // per j: (wa0,wa0,wa1,wa1)(wa2..wa3)(wa4..wa5)(w2,w2,hd,hd)
    __shared__ float4 ea2[NN * 3];   // per s: duplicated ea pairs (e0,e0,e1,e1)(e2,e2,e3,e3)(e4,e4,e5,e5)
    __shared__ float  wexp[NN];      // softmax weights (per 128-src group max)
    __shared__ float4 plog[4 * 32];  // partial logits from warps 4-7
    __shared__ float  pm[4], ps[4], pacc[8 * H];
    __shared__ float  part4[4 * H], agg_sh[H], h_sh[H], tmp_sh[H], hid_sh[H], hn_sh[H], red_sh[4];

    // Prologue: weight table (duplicated for f32x2) + Hd row
    if (t < H) {
        int j = t;
        float w0 = attW1e[0 * H + j], w1 = attW1e[1 * H + j];
        float w2 = attW1e[2 * H + j], w3 = attW1e[3 * H + j];
        float w4 = attW1e[4 * H + j], w5 = attW1e[5 * H + j];
        float a2v = attW2[j];
        float hdv = g_Hd[d * H + j];
        wa4[j * 4 + 0] = make_float4(w0, w0, w1, w1);
        wa4[j * 4 + 1] = make_float4(w2, w2, w3, w3);
        wa4[j * 4 + 2] = make_float4(w4, w4, w5, w5);
        wa4[j * 4 + 3] = make_float4(a2v, a2v, hdv, hdv);
    }

    const float* HsT = g_HsT[rb];
    const float* AvL = g_Av[rb];
    const int sa = wg * 128 + 4 * lane;   // 4 srcs: sa..sa+3

    // Load ea for the 4 srcs (float4 from eaT, contiguous) — registers
    float4 eaq[ED];
#pragma unroll
    for (int k = 0; k < ED; k++)
        eaq[k] = *(const float4*)(g_eaT + (size_t)k * EE + d * NN + sa);

    // Warps 0-3 publish duplicated ea pairs for pass 2
    if (w < 4) {
        ea2[(sa + 0) * 3 + 0] = make_float4(eaq[0].x, eaq[0].x, eaq[1].x, eaq[1].x);
        ea2[(sa + 0) * 3 + 1] = make_float4(eaq[2].x, eaq[2].x, eaq[3].x, eaq[3].x);
        ea2[(sa + 0) * 3 + 2] = make_float4(eaq[4].x, eaq[4].x, eaq[5].x, eaq[5].x);
        ea2[(sa + 1) * 3 + 0] = make_float4(eaq[0].y, eaq[0].y, eaq[1].y, eaq[1].y);
        ea2[(sa + 1) * 3 + 1] = make_float4(eaq[2].y, eaq[2].y, eaq[3].y, eaq[3].y);
        ea2[(sa + 1) * 3 + 2] = make_float4(eaq[4].y, eaq[4].y, eaq[5].y, eaq[5].y);
        ea2[(sa + 2) * 3 + 0] = make_float4(eaq[0].z, eaq[0].z, eaq[1].z, eaq[1].z);
        ea2[(sa + 2) * 3 + 1] = make_float4(eaq[2].z, eaq[2].z, eaq[3].z, eaq[3].z);
        ea2[(sa + 2) * 3 + 2] = make_float4(eaq[4].z, eaq[4].z, eaq[5].z, eaq[5].z);
        ea2[(sa + 3) * 3 + 0] = make_float4(eaq[0].w, eaq[0].w, eaq[1].w, eaq[1].w);
        ea2[(sa + 3) * 3 + 1] = make_float4(eaq[2].w, eaq[2].w, eaq[3].w, eaq[3].w);
        ea2[(sa + 3) * 3 + 2] = make_float4(eaq[4].w, eaq[4].w, eaq[5].w, eaq[5].w);
    }
    __syncthreads();

    // ---- Pass 1: partial attention logits over this warp's j-half ----
    float2 lgA = make_float2(0.f, 0.f), lgB = make_float2(0.f, 0.f);
#pragma unroll 8
    for (int jj = 0; jj < 32; jj++) {
        int j = jbase + jj;
        float4 a0 = wa4[j * 4 + 0];
        float4 a1 = wa4[j * 4 + 1];
        float4 a2 = wa4[j * 4 + 2];
        float4 a3 = wa4[j * 4 + 3];
        float4 hs4 = *(const float4*)(HsT + j * NN + sa);
        float2 hdd = make_float2(a3.z, a3.w);
        float2 zA = fadd2(make_float2(hs4.x, hs4.y), hdd);
        float2 zB = fadd2(make_float2(hs4.z, hs4.w), hdd);
        zA = ffma2(make_float2(eaq[0].x, eaq[0].y), make_float2(a0.x, a0.y), zA);
        zB = ffma2(make_float2(eaq[0].z, eaq[0].w), make_float2(a0.x, a0.y), zB);
        zA = ffma2(make_float2(eaq[1].x, eaq[1].y), make_float2(a0.z, a0.w), zA);
        zB = ffma2(make_float2(eaq[1].z, eaq[1].w), make_float2(a0.z, a0.w), zB);
        zA = ffma2(make_float2(eaq[2].x, eaq[2].y), make_float2(a1.x, a1.y), zA);
        zB = ffma2(make_float2(eaq[2].z, eaq[2].w), make_float2(a1.x, a1.y), zB);
        zA = ffma2(make_float2(eaq[3].x, eaq[3].y), make_float2(a1.z, a1.w), zA);
        zB = ffma2(make_float2(eaq[3].z, eaq[3].w), make_float2(a1.z, a1.w), zB);
        zA = ffma2(make_float2(eaq[4].x, eaq[4].y), make_float2(a2.x, a2.y), zA);
        zB = ffma2(make_float2(eaq[4].z, eaq[4].w), make_float2(a2.x, a2.y), zB);
        zA = ffma2(make_float2(eaq[5].x, eaq[5].y), make_float2(a2.z, a2.w), zA);
        zB = ffma2(make_float2(eaq[5].z, eaq[5].w), make_float2(a2.z, a2.w), zB);
        // leaky_relu(., 0.2)
        float2 sA = fmul2(zA, make_float2(0.2f, 0.2f));
        float2 sB = fmul2(zB, make_float2(0.2f, 0.2f));
        zA.x = fmaxf(zA.x, sA.x); zA.y = fmaxf(zA.y, sA.y);
        zB.x = fmaxf(zB.x, sB.x); zB.y = fmaxf(zB.y, sB.y);
        float2 w22 = make_float2(a3.x, a3.y);
        lgA = ffma2(zA, w22, lgA);
        lgB = ffma2(zB, w22, lgB);
    }

    // Exchange j-halves, then per-group register softmax (warps 0-3)
    if (w >= 4) plog[wg * 32 + lane] = make_float4(lgA.x, lgA.y, lgB.x, lgB.y);
    __syncthreads();
    if (w < 4) {
        float4 p = plog[wg * 32 + lane];
        lgA.x += p.x; lgA.y += p.y; lgB.x += p.z; lgB.y += p.w;
        float m = warp_max(fmaxf(fmaxf(lgA.x, lgA.y), fmaxf(lgB.x, lgB.y)));
        float e0 = __expf(lgA.x - m), e1 = __expf(lgA.y - m);
        float e2 = __expf(lgB.x - m), e3 = __expf(lgB.y - m);
        float s_w = warp_sum(e0 + e1 + e2 + e3);
        if (lane == 0) { pm[wg] = m; ps[wg] = s_w; }
        *(float4*)(wexp + sa) = make_float4(e0, e1, e2, e3);
    }
    __syncthreads();

    // ---- Pass 2: alpha-weighted value aggregation (f32x2, 2 dims/lane) ----
    const int j0 = 2 * lane;
    float2 wv[ED];
#pragma unroll
    for (int k = 0; k < ED; k++) wv[k] = *(const float2*)(valW1e + k * H + j0);

    float2 acc = make_float2(0.f, 0.f);
    const int s0 = w * 64;
#pragma unroll 2
    for (int i = 0; i < 64; i += 4) {
        float4 wg4 = *(const float4*)(wexp + s0 + i);
#pragma unroll
        for (int u = 0; u < 4; u++) {
            int s = s0 + i + u;
            float4 d0 = ea2[s * 3 + 0];
            float4 d1 = ea2[s * 3 + 1];
            float4 d2 = ea2[s * 3 + 2];
            float2 p = *(const float2*)(AvL + s * H + j0);
            p = ffma2(make_float2(d0.x, d0.y), wv[0], p);
            p = ffma2(make_float2(d0.z, d0.w), wv[1], p);
            p = ffma2(make_float2(d1.x, d1.y), wv[2], p);
            p = ffma2(make_float2(d1.z, d1.w), wv[3], p);
            p = ffma2(make_float2(d2.x, d2.y), wv[4], p);
            p = ffma2(make_float2(d2.z, d2.w), wv[5], p);
            p.x = fmaxf(p.x, 0.f);
            p.y = fmaxf(p.y, 0.f);
            float wt = (u == 0) ? wg4.x : (u == 1) ? wg4.y : (u == 2) ? wg4.z : wg4.w;
            acc = ffma2(make_float2(wt, wt), p, acc);
        }
    }
    *(float2*)(pacc + w * H + j0) = acc;
    __syncthreads();

    // ---- Combine 4 group softmax partials over 8 warp accumulators ----
    if (t < H) {
        float M = fmaxf(fmaxf(pm[0], pm[1]), fmaxf(pm[2], pm[3]));
        float sc0 = __expf(pm[0] - M), sc1 = __expf(pm[1] - M);
        float sc2 = __expf(pm[2] - M), sc3 = __expf(pm[3] - M);
        float stot = ps[0] * sc0 + ps[1] * sc1 + ps[2] * sc2 + ps[3] * sc3;
        float a = (pacc[0 * H + t] + pacc[1 * H + t]) * sc0
                + (pacc[2 * H + t] + pacc[3 * H + t]) * sc1
                + (pacc[4 * H + t] + pacc[5 * H + t]) * sc2
                + (pacc[6 * H + t] + pacc[7 * H + t]) * sc3;
        agg_sh[t] = a / stot;
        h_sh[t]   = g_h[d * H + t];
    }
    __syncthreads();

    // ---- Node phase, 4-way k-split matvecs over all 256 threads ----
    const int o = t & 63, q = t >> 6;

    // stage 1: tmp = val_b2 + agg @ val_w2
    {
        float p = 0.f;
        int k0 = q * 16;
#pragma unroll
        for (int kk = 0; kk < 16; kk++) p += agg_sh[k0 + kk] * valW2[(k0 + kk) * H + o];
        part4[q * H + o] = p;
    }
    __syncthreads();
    if (t < H) tmp_sh[t] = valB2[t] + part4[t] + part4[H + t] + part4[2 * H + t] + part4[3 * H + t];
    __syncthreads();

    // stage 2: hid = relu(upd_b1 + [h,tmp] @ upd_w1)
    {
        const float* srcv = (q < 2) ? h_sh : tmp_sh;
        int koff = (q & 1) * 32;
        int rbase = ((q >= 2) ? H : 0) + koff;
        float p = 0.f;
#pragma unroll
        for (int kk = 0; kk < 32; kk++) p += srcv[koff + kk] * updW1[(rbase + kk) * H + o];
        part4[q * H + o] = p;
    }
    __syncthreads();
    if (t < H) hid_sh[t] = fmaxf(updB1[t] + part4[t] + part4[H + t] + part4[2 * H + t] + part4[3 * H + t], 0.f);
    __syncthreads();

    // stage 3: u = upd_b2 + hid @ upd_w2
    {
        float p = 0.f;
        int k0 = q * 16;
#pragma unroll
        for (int kk = 0; kk < 16; kk++) p += hid_sh[k0 + kk] * updW2[(k0 + kk) * H + o];
        part4[q * H + o] = p;
    }
    __syncthreads();

    // residual + LayerNorm (threads 0..63 = warps 0,1)
    float r = 0.f, dr = 0.f;
    if (t < H) {
        float u = updB2[t] + part4[t] + part4[H + t] + part4[2 * H + t] + part4[3 * H + t];
        r = u + h_sh[t];
        float s1 = warp_sum(r);
        if (lane == 0) red_sh[w] = s1;
    }
    __syncthreads();
    if (t < H) {
        float mu = (red_sh[0] + red_sh[1]) * (1.0f / H);
        dr = r - mu;
        float s2 = warp_sum(dr * dr);
        if (lane == 0) red_sh[w + 2] = s2;
    }
    __syncthreads();
    if (t < H) {
        float var = (red_sh[2] + red_sh[3]) * (1.0f / H);
        float hn = lng[t] * dr * rsqrtf(var + LN_EPS) + lnb[t];
        hn_sh[t] = hn;
        if (!last) g_h[d * H + t] = hn;
    }
    __syncthreads();

    if (!last) {
        if (t < H)
            compute_tables(d, t, wb, hn_sh, nattW1, nattB1, nvalW1, nvalB1);
    } else {
        if (t < H) {
            float dh = decB1[t];
#pragma unroll 8
            for (int k = 0; k < H; k++) dh += hn_sh[k] * decW1[k * H + t];
            dh = fmaxf(dh, 0.f);
            float p = dh * decW2[t];
            float psum = warp_sum(p);
            if (lane == 0) red_sh[w] = psum;
        }
        __syncthreads();
        if (t == 0) out[d] = red_sh[0] + red_sh[1] + decB2[0];
    }
}

extern "C" void kernel_launch(void* const* d_in, const int* in_sizes, int n_in,
                              void* d_out, int out_size)
{
    const float* x      = (const float*)d_in[0];
    const float* ea     = (const float*)d_in[1];
    const float* enc_w1 = (const float*)d_in[2];
    const float* enc_b1 = (const float*)d_in[3];
    const float* enc_w2 = (const float*)d_in[4];
    const float* enc_b2 = (const float*)d_in[5];
    const float* att_w1 = (const float*)d_in[6];   // [4,134,64]
    const float* att_b1 = (const float*)d_in[7];   // [4,64]
    const float* att_w2 = (const float*)d_in[8];   // [4,64,1]
    // d_in[9] = att_b2 — cancels inside softmax, unused
    const float* val_w1 = (const float*)d_in[10];  // [4,70,64]
    const float* val_b1 = (const float*)d_in[11];  // [4,64]
    const float* val_w2 = (const float*)d_in[12];  // [4,64,64]
    const float* val_b2 = (const float*)d_in[13];  // [4,64]
    const float* upd_w1 = (const float*)d_in[14];  // [4,128,64]
    const float* upd_b1 = (const float*)d_in[15];  // [4,64]
    const float* upd_w2 = (const float*)d_in[16];  // [4,64,64]
    const float* upd_b2 = (const float*)d_in[17];  // [4,64]
    const float* ln_g   = (const float*)d_in[18];  // [4,64]
    const float* ln_b   = (const float*)d_in[19];  // [4,64]
    const float* dec_w1 = (const float*)d_in[20];
    const float* dec_b1 = (const float*)d_in[21];
    const float* dec_w2 = (const float*)d_in[22];
    const float* dec_b2 = (const float*)d_in[23];
    // d_in[24] = edge_index: src=e/512, dst=e%512 (structure exploited directly)

    float* out = (float*)d_out;

    ea_transpose_kernel<<<dim3(16, 16), 256>>>(ea);
    enc_kernel<<<NN, H>>>(x, enc_w1, enc_b1, enc_w2, enc_b2,
                          att_w1, att_b1, val_w1, val_b1);

    for (int l = 0; l < NL; l++) {
        int last = (l == NL - 1);
        int nl = (l + 1) % NL;      // dummy-but-valid pointers on last layer
        int rb = l & 1;             // enc wrote buffer 0; layer l reads l&1, writes (l&1)^1
        layer_kernel<<<NN, 256>>>(att_w1 + (l * 134 + 128) * H,
                                  att_w2 + l * H,
                                  val_w1 + (l * 70 + 64) * H,
                                  val_w2 + l * H * H, val_b2 + l * H,
                                  upd_w1 + l * 2 * H * H, upd_b1 + l * H,
                                  upd_w2 + l * H * H, upd_b2 + l * H,
                                  ln_g + l * H, ln_b + l * H,
                                  att_w1 + nl * 134 * H, att_b1 + nl * H,
                                  val_w1 + nl * 70 * H, val_b1 + nl * H,
                                  dec_w1, dec_b1, dec_w2, dec_b2,
                                  out, rb, last);
    }
}

// round 5
// speedup vs baseline: 2.4046x; 1.0721x over previous
#include <cuda_runtime.h>
#include <string.h>

#define NN 512
#define H  64
#define ED 6
#define NL 4
#define EE (NN*NN)
#define LN_EPS 1e-5f

// Scratch (device globals: no allocations allowed)
__device__ float g_h  [NN*H];
__device__ float g_Hd [NN*H];         // dst-side attention proj (+att_b1), row-major
__device__ float g_HsT[2][H*NN];      // src-side attention proj, DIM-MAJOR [j][s], double buffered
__device__ float g_Av [2][NN*H];      // src-side value proj (+val_b1), row-major, double buffered
__device__ float g_eaT[ED*EE];        // edge_attr transposed: eaT[k][d][s]

__device__ __forceinline__ float warp_sum(float v) {
#pragma unroll
    for (int o = 16; o; o >>= 1) v += __shfl_xor_sync(0xffffffffu, v, o);
    return v;
}
__device__ __forceinline__ float warp_max(float v) {
#pragma unroll
    for (int o = 16; o; o >>= 1) v = fmaxf(v, __shfl_xor_sync(0xffffffffu, v, o));
    return v;
}

// Packed fp32x2 ops (sm_103a): 2 fp32 FMAs per instruction
__device__ __forceinline__ float2 ffma2(float2 a, float2 b, float2 c) {
    unsigned long long ua, ub, uc, ur;
    memcpy(&ua, &a, 8); memcpy(&ub, &b, 8); memcpy(&uc, &c, 8);
    asm("fma.rn.f32x2 %0, %1, %2, %3;" : "=l"(ur) : "l"(ua), "l"(ub), "l"(uc));
    float2 r; memcpy(&r, &ur, 8); return r;
}
__device__ __forceinline__ float2 fadd2(float2 a, float2 b) {
    unsigned long long ua, ub, ur;
    memcpy(&ua, &a, 8); memcpy(&ub, &b, 8);
    asm("add.rn.f32x2 %0, %1, %2;" : "=l"(ur) : "l"(ua), "l"(ub));
    float2 r; memcpy(&r, &ur, 8); return r;
}
__device__ __forceinline__ float2 fmul2(float2 a, float2 b) {
    unsigned long long ua, ub, ur;
    memcpy(&ua, &a, 8); memcpy(&ub, &b, 8);
    asm("mul.rn.f32x2 %0, %1, %2;" : "=l"(ur) : "l"(ua), "l"(ub));
    float2 r; memcpy(&r, &ur, 8); return r;
}
__device__ __forceinline__ float2 dup2(float v) { return make_float2(v, v); }

// Per-node tables: Hd = h@Wa[0:64]+b1a (row), HsT = h@Wa[64:128] (dim-major), Av = h@Wv[0:64]+b1v (row)
__device__ __forceinline__ void compute_tables(
    int d, int t, int wb, const float* h_sh,
    const float* __restrict__ attW1, const float* __restrict__ attB1,
    const float* __restrict__ valW1, const float* __restrict__ valB1)
{
    float ad = attB1[t], as = 0.f, av = valB1[t];
#pragma unroll 8
    for (int k = 0; k < H; k++) {
        float hk = h_sh[k];
        ad += hk * attW1[k * H + t];
        as += hk * attW1[(H + k) * H + t];
        av += hk * valW1[k * H + t];
    }
    g_Hd[d * H + t]       = ad;
    g_HsT[wb][t * NN + d] = as;
    g_Av[wb][d * H + t]   = av;
}

// Transpose edge_attr: ea[s][d][k] -> eaT[k][d][s]. grid (16,16), block 256.
__global__ void __launch_bounds__(256) ea_transpose_kernel(const float* __restrict__ ea)
{
    __shared__ float t_sh[ED][32][33];
    const int t = threadIdx.x, w = t >> 5, lane = t & 31;
    const int bs = blockIdx.x * 32, bd = blockIdx.y * 32;

#pragma unroll
    for (int rr = 0; rr < 4; rr++) {
        int s_loc = w + rr * 8;
        const float* base = ea + ((size_t)(bs + s_loc) * NN + bd) * ED + lane * ED;
        float2 v0 = *(const float2*)(base);
        float2 v1 = *(const float2*)(base + 2);
        float2 v2 = *(const float2*)(base + 4);
        t_sh[0][lane][s_loc] = v0.x; t_sh[1][lane][s_loc] = v0.y;
        t_sh[2][lane][s_loc] = v1.x; t_sh[3][lane][s_loc] = v1.y;
        t_sh[4][lane][s_loc] = v2.x; t_sh[5][lane][s_loc] = v2.y;
    }
    __syncthreads();
#pragma unroll
    for (int idx = t; idx < ED * 32 * 32; idx += 256) {
        int k = idx >> 10, r = idx & 1023, dl = r >> 5, sl = r & 31;
        g_eaT[(size_t)k * EE + (size_t)(bd + dl) * NN + bs + sl] = t_sh[k][dl][sl];
    }
}

// Encoder: h = relu(x@W1+b1)@W2+b2, then layer-0 tables (buffer 0). grid=512, block=64
__global__ void __launch_bounds__(H) enc_kernel(
    const float* __restrict__ x,
    const float* __restrict__ ew1, const float* __restrict__ eb1,
    const float* __restrict__ ew2, const float* __restrict__ eb2,
    const float* __restrict__ attW1, const float* __restrict__ attB1,
    const float* __restrict__ valW1, const float* __restrict__ valB1)
{
    int d = blockIdx.x, t = threadIdx.x;
    __shared__ float xs[ED], hid[H], hsn[H];
    if (t < ED) xs[t] = x[d * ED + t];
    __syncthreads();
    float a = eb1[t];
#pragma unroll
    for (int k = 0; k < ED; k++) a += xs[k] * ew1[k * H + t];
    hid[t] = fmaxf(a, 0.f);
    __syncthreads();
    float hv = eb2[t];
#pragma unroll 8
    for (int k = 0; k < H; k++) hv += hid[k] * ew2[k * H + t];
    g_h[d * H + t] = hv;
    hsn[t] = hv;
    __syncthreads();
    compute_tables(d, t, 0, hsn, attW1, attB1, valW1, valB1);
}

// Fused layer: one block per dst node d. 256 threads = 8 warps.
// Pass 1 (j-split): warps 0-3 own srcs [wg*128, wg*128+128) with j in [0,32);
// warps 4-7 same srcs, j in [32,64). Lane owns 4 srcs. Weight table stored
// NON-duplicated in smem (2 LDS.128/j); duplicated f32x2 operands built via
// register MOVs (ALU pipe). Partial logits exchanged; warps 0-3 do softmax.
// Pass 2: warp w owns srcs [w*64,+64), dims (2*lane,2*lane+1); ea packed
// non-duplicated (LDS.128+LDS.64/s). Node MLP + LN + next tables fused.
__global__ void __launch_bounds__(256, 3) layer_kernel(
    const float* __restrict__ attW1e,   // [6,64] edge rows of att_w1[l]
    const float* __restrict__ attW2,    // [64]
    const float* __restrict__ valW1e,   // [6,64] edge rows of val_w1[l]
    const float* __restrict__ valW2, const float* __restrict__ valB2,
    const float* __restrict__ updW1, const float* __restrict__ updB1,
    const float* __restrict__ updW2, const float* __restrict__ updB2,
    const float* __restrict__ lng, const float* __restrict__ lnb,
    const float* __restrict__ nattW1, const float* __restrict__ nattB1,
    const float* __restrict__ nvalW1, const float* __restrict__ nvalB1,
    const float* __restrict__ decW1, const float* __restrict__ decB1,
    const float* __restrict__ decW2, const float* __restrict__ decB2,
    float* __restrict__ out, int rb, int last)
{
    const int d = blockIdx.x;
    const int t = threadIdx.x, w = t >> 5, lane = t & 31;
    const int wg = w & 3;            // src group
    const int jbase = (w >> 2) * 32; // j half
    const int wb = rb ^ 1;

    __shared__ float4 waA[H];        // per j: (wa0,wa1,wa2,wa3)
    __shared__ float4 waB[H];        // per j: (wa4,wa5,w2,hd)
    __shared__ float4 eaA[NN];       // per s: (e0,e1,e2,e3)
    __shared__ float2 eaB[NN];       // per s: (e4,e5)
    __shared__ float  wexp[NN];      // softmax weights
    __shared__ float4 plog[4 * 32];  // partial logits from warps 4-7
    __shared__ float  pm[4], ps[4], pacc[8 * H];
    __shared__ float  part4[4 * H], agg_sh[H], h_sh[H], tmp_sh[H], hid_sh[H], hn_sh[H], red_sh[4];

    // Prologue: weight table (non-duplicated) + Hd row
    if (t < H) {
        int j = t;
        waA[j] = make_float4(attW1e[0 * H + j], attW1e[1 * H + j],
                             attW1e[2 * H + j], attW1e[3 * H + j]);
        waB[j] = make_float4(attW1e[4 * H + j], attW1e[5 * H + j],
                             attW2[j], g_Hd[d * H + j]);
    }

    const float* HsT = g_HsT[rb];
    const float* AvL = g_Av[rb];
    const int sa = wg * 128 + 4 * lane;   // 4 srcs: sa..sa+3

    // Load ea for the 4 srcs (float4 from eaT, contiguous) — registers
    float4 eaq[ED];
#pragma unroll
    for (int k = 0; k < ED; k++)
        eaq[k] = *(const float4*)(g_eaT + (size_t)k * EE + d * NN + sa);

    // Warps 0-3 publish packed (non-duplicated) ea for pass 2
    if (w < 4) {
#pragma unroll
        for (int u = 0; u < 4; u++) {
            float e0 = (u == 0) ? eaq[0].x : (u == 1) ? eaq[0].y : (u == 2) ? eaq[0].z : eaq[0].w;
            float e1 = (u == 0) ? eaq[1].x : (u == 1) ? eaq[1].y : (u == 2) ? eaq[1].z : eaq[1].w;
            float e2 = (u == 0) ? eaq[2].x : (u == 1) ? eaq[2].y : (u == 2) ? eaq[2].z : eaq[2].w;
            float e3 = (u == 0) ? eaq[3].x : (u == 1) ? eaq[3].y : (u == 2) ? eaq[3].z : eaq[3].w;
            float e4 = (u == 0) ? eaq[4].x : (u == 1) ? eaq[4].y : (u == 2) ? eaq[4].z : eaq[4].w;
            float e5 = (u == 0) ? eaq[5].x : (u == 1) ? eaq[5].y : (u == 2) ? eaq[5].z : eaq[5].w;
            eaA[sa + u] = make_float4(e0, e1, e2, e3);
            eaB[sa + u] = make_float2(e4, e5);
        }
    }
    __syncthreads();

    // Src pairs for f32x2: A = (sa, sa+1), B = (sa+2, sa+3)
    float2 eA[ED], eB[ED];
#pragma unroll
    for (int k = 0; k < ED; k++) {
        eA[k] = make_float2(eaq[k].x, eaq[k].y);
        eB[k] = make_float2(eaq[k].z, eaq[k].w);
    }

    // ---- Pass 1: partial attention logits over this warp's j-half ----
    float2 lgA = make_float2(0.f, 0.f), lgB = make_float2(0.f, 0.f);
#pragma unroll 8
    for (int jj = 0; jj < 32; jj++) {
        int j = jbase + jj;
        float4 wAv = waA[j];
        float4 wBv = waB[j];
        float4 hs4 = *(const float4*)(HsT + j * NN + sa);
        float2 W0 = dup2(wAv.x), W1 = dup2(wAv.y), W2 = dup2(wAv.z), W3 = dup2(wAv.w);
        float2 W4 = dup2(wBv.x), W5 = dup2(wBv.y), Wo = dup2(wBv.z), HD = dup2(wBv.w);
        // split z into two 3-deep chains per src pair (4 independent chains)
        float2 zA  = fadd2(make_float2(hs4.x, hs4.y), HD);
        float2 zB  = fadd2(make_float2(hs4.z, hs4.w), HD);
        float2 zA2 = fmul2(eA[3], W3);
        float2 zB2 = fmul2(eB[3], W3);
        zA  = ffma2(eA[0], W0, zA);   zB  = ffma2(eB[0], W0, zB);
        zA2 = ffma2(eA[4], W4, zA2);  zB2 = ffma2(eB[4], W4, zB2);
        zA  = ffma2(eA[1], W1, zA);   zB  = ffma2(eB[1], W1, zB);
        zA2 = ffma2(eA[5], W5, zA2);  zB2 = ffma2(eB[5], W5, zB2);
        zA  = ffma2(eA[2], W2, zA);   zB  = ffma2(eB[2], W2, zB);
        zA  = fadd2(zA, zA2);         zB  = fadd2(zB, zB2);
        // leaky_relu(., 0.2)
        float2 sA = fmul2(zA, make_float2(0.2f, 0.2f));
        float2 sB = fmul2(zB, make_float2(0.2f, 0.2f));
        zA.x = fmaxf(zA.x, sA.x); zA.y = fmaxf(zA.y, sA.y);
        zB.x = fmaxf(zB.x, sB.x); zB.y = fmaxf(zB.y, sB.y);
        lgA = ffma2(zA, Wo, lgA);
        lgB = ffma2(zB, Wo, lgB);
    }

    // Exchange j-halves, then per-group register softmax (warps 0-3)
    if (w >= 4) plog[wg * 32 + lane] = make_float4(lgA.x, lgA.y, lgB.x, lgB.y);
    __syncthreads();
    if (w < 4) {
        float4 p = plog[wg * 32 + lane];
        lgA.x += p.x; lgA.y += p.y; lgB.x += p.z; lgB.y += p.w;
        float m = warp_max(fmaxf(fmaxf(lgA.x, lgA.y), fmaxf(lgB.x, lgB.y)));
        float e0 = __expf(lgA.x - m), e1 = __expf(lgA.y - m);
        float e2 = __expf(lgB.x - m), e3 = __expf(lgB.y - m);
        float s_w = warp_sum(e0 + e1 + e2 + e3);
        if (lane == 0) { pm[wg] = m; ps[wg] = s_w; }
        *(float4*)(wexp + sa) = make_float4(e0, e1, e2, e3);
    }
    __syncthreads();

    // ---- Pass 2: alpha-weighted value aggregation (f32x2, 2 dims/lane) ----
    const int j0 = 2 * lane;
    float2 wv[ED];
#pragma unroll
    for (int k = 0; k < ED; k++) wv[k] = *(const float2*)(valW1e + k * H + j0);

    float2 acc0 = make_float2(0.f, 0.f), acc1 = make_float2(0.f, 0.f);
    const int s0 = w * 64;
#pragma unroll 2
    for (int i = 0; i < 64; i += 4) {
        float4 wg4 = *(const float4*)(wexp + s0 + i);
#pragma unroll
        for (int u = 0; u < 4; u++) {
            int s = s0 + i + u;
            float4 dA = eaA[s];
            float2 dB = eaB[s];
            float2 p = *(const float2*)(AvL + s * H + j0);
            p = ffma2(dup2(dA.x), wv[0], p);
            p = ffma2(dup2(dA.y), wv[1], p);
            p = ffma2(dup2(dA.z), wv[2], p);
            p = ffma2(dup2(dA.w), wv[3], p);
            p = ffma2(dup2(dB.x), wv[4], p);
            p = ffma2(dup2(dB.y), wv[5], p);
            p.x = fmaxf(p.x, 0.f);
            p.y = fmaxf(p.y, 0.f);
            float wt = (u == 0) ? wg4.x : (u == 1) ? wg4.y : (u == 2) ? wg4.z : wg4.w;
            if (u & 1) acc1 = ffma2(dup2(wt), p, acc1);
            else       acc0 = ffma2(dup2(wt), p, acc0);
        }
    }
    acc0 = fadd2(acc0, acc1);
    *(float2*)(pacc + w * H + j0) = acc0;
    __syncthreads();

    // ---- Combine 4 group softmax partials over 8 warp accumulators ----
    if (t < H) {
        float M = fmaxf(fmaxf(pm[0], pm[1]), fmaxf(pm[2], pm[3]));
        float sc0 = __expf(pm[0] - M), sc1 = __expf(pm[1] - M);
        float sc2 = __expf(pm[2] - M), sc3 = __expf(pm[3] - M);
        float stot = ps[0] * sc0 + ps[1] * sc1 + ps[2] * sc2 + ps[3] * sc3;
        float a = (pacc[0 * H + t] + pacc[1 * H + t]) * sc0
                + (pacc[2 * H + t] + pacc[3 * H + t]) * sc1
                + (pacc[4 * H + t] + pacc[5 * H + t]) * sc2
                + (pacc[6 * H + t] + pacc[7 * H + t]) * sc3;
        agg_sh[t] = a / stot;
        h_sh[t]   = g_h[d * H + t];
    }
    __syncthreads();

    // ---- Node phase, 4-way k-split matvecs over all 256 threads ----
    const int o = t & 63, q = t >> 6;

    // stage 1: tmp = val_b2 + agg @ val_w2
    {
        float p = 0.f;
        int k0 = q * 16;
#pragma unroll
        for (int kk = 0; kk < 16; kk++) p += agg_sh[k0 + kk] * valW2[(k0 + kk) * H + o];
        part4[q * H + o] = p;
    }
    __syncthreads();
    if (t < H) tmp_sh[t] = valB2[t] + part4[t] + part4[H + t] + part4[2 * H + t] + part4[3 * H + t];
    __syncthreads();

    // stage 2: hid = relu(upd_b1 + [h,tmp] @ upd_w1)
    {
        const float* srcv = (q < 2) ? h_sh : tmp_sh;
        int koff = (q & 1) * 32;
        int rbase = ((q >= 2) ? H : 0) + koff;
        float p = 0.f;
#pragma unroll
        for (int kk = 0; kk < 32; kk++) p += srcv[koff + kk] * updW1[(rbase + kk) * H + o];
        part4[q * H + o] = p;
    }
    __syncthreads();
    if (t < H) hid_sh[t] = fmaxf(updB1[t] + part4[t] + part4[H + t] + part4[2 * H + t] + part4[3 * H + t], 0.f);
    __syncthreads();

    // stage 3: u = upd_b2 + hid @ upd_w2
    {
        float p = 0.f;
        int k0 = q * 16;
#pragma unroll
        for (int kk = 0; kk < 16; kk++) p += hid_sh[k0 + kk] * updW2[(k0 + kk) * H + o];
        part4[q * H + o] = p;
    }
    __syncthreads();

    // residual + LayerNorm (threads 0..63 = warps 0,1; fused sum/sumsq)
    float r = 0.f, dr = 0.f;
    if (t < H) {
        float u = updB2[t] + part4[t] + part4[H + t] + part4[2 * H + t] + part4[3 * H + t];
        r = u + h_sh[t];
        float s1 = warp_sum(r);
        float s2 = warp_sum(r * r);
        if (lane == 0) { red_sh[w] = s1; red_sh[w + 2] = s2; }
    }
    __syncthreads();
    if (t < H) {
        float mu  = (red_sh[0] + red_sh[1]) * (1.0f / H);
        float ex2 = (red_sh[2] + red_sh[3]) * (1.0f / H);
        float var = ex2 - mu * mu;
        dr = r - mu;
        float hn = lng[t] * dr * rsqrtf(var + LN_EPS) + lnb[t];
        hn_sh[t] = hn;
        if (!last) g_h[d * H + t] = hn;
    }
    __syncthreads();

    if (!last) {
        if (t < H)
            compute_tables(d, t, wb, hn_sh, nattW1, nattB1, nvalW1, nvalB1);
    } else {
        if (t < H) {
            float dh = decB1[t];
#pragma unroll 8
            for (int k = 0; k < H; k++) dh += hn_sh[k] * decW1[k * H + t];
            dh = fmaxf(dh, 0.f);
            float p = dh * decW2[t];
            float psum = warp_sum(p);
            if (lane == 0) red_sh[w] = psum;
        }
        __syncthreads();
        if (t == 0) out[d] = red_sh[0] + red_sh[1] + decB2[0];
    }
}

extern "C" void kernel_launch(void* const* d_in, const int* in_sizes, int n_in,
                              void* d_out, int out_size)
{
    const float* x      = (const float*)d_in[0];
    const float* ea     = (const float*)d_in[1];
    const float* enc_w1 = (const float*)d_in[2];
    const float* enc_b1 = (const float*)d_in[3];
    const float* enc_w2 = (const float*)d_in[4];
    const float* enc_b2 = (const float*)d_in[5];
    const float* att_w1 = (const float*)d_in[6];   // [4,134,64]
    const float* att_b1 = (const float*)d_in[7];   // [4,64]
    const float* att_w2 = (const float*)d_in[8];   // [4,64,1]
    // d_in[9] = att_b2 — cancels inside softmax, unused
    const float* val_w1 = (const float*)d_in[10];  // [4,70,64]
    const float* val_b1 = (const float*)d_in[11];  // [4,64]
    const float* val_w2 = (const float*)d_in[12];  // [4,64,64]
    const float* val_b2 = (const float*)d_in[13];  // [4,64]
    const float* upd_w1 = (const float*)d_in[14];  // [4,128,64]
    const float* upd_b1 = (const float*)d_in[15];  // [4,64]
    const float* upd_w2 = (const float*)d_in[16];  // [4,64,64]
    const float* upd_b2 = (const float*)d_in[17];  // [4,64]
    const float* ln_g   = (const float*)d_in[18];  // [4,64]
    const float* ln_b   = (const float*)d_in[19];  // [4,64]
    const float* dec_w1 = (const float*)d_in[20];
    const float* dec_b1 = (const float*)d_in[21];
    const float* dec_w2 = (const float*)d_in[22];
    const float* dec_b2 = (const float*)d_in[23];
    // d_in[24] = edge_index: src=e/512, dst=e%512 (structure exploited directly)

    float* out = (float*)d_out;

    ea_transpose_kernel<<<dim3(16, 16), 256>>>(ea);
    enc_kernel<<<NN, H>>>(x, enc_w1, enc_b1, enc_w2, enc_b2,
                          att_w1, att_b1, val_w1, val_b1);

    for (int l = 0; l < NL; l++) {
        int last = (l == NL - 1);
        int nl = (l + 1) % NL;      // dummy-but-valid pointers on last layer
        int rb = l & 1;             // enc wrote buffer 0; layer l reads l&1, writes (l&1)^1
        layer_kernel<<<NN, 256>>>(att_w1 + (l * 134 + 128) * H,
                                  att_w2 + l * H,
                                  val_w1 + (l * 70 + 64) * H,
                                  val_w2 + l * H * H, val_b2 + l * H,
                                  upd_w1 + l * 2 * H * H, upd_b1 + l * H,
                                  upd_w2 + l * H * H, upd_b2 + l * H,
                                  ln_g + l * H, ln_b + l * H,
                                  att_w1 + nl * 134 * H, att_b1 + nl * H,
                                  val_w1 + nl * 70 * H, val_b1 + nl * H,
                                  dec_w1, dec_b1, dec_w2, dec_b2,
                                  out, rb, last);
    }
}

// round 6
// speedup vs baseline: 2.6915x; 1.1193x over previous
#include <cuda_runtime.h>
#include <string.h>

#define NN 512
#define H  64
#define ED 6
#define NL 4
#define EE (NN*NN)
#define LN_EPS 1e-5f

// Scratch (device globals: no allocations allowed)
__device__ float g_h  [NN*H];
__device__ float g_Hd [NN*H];         // dst-side attention proj (+att_b1), row-major
__device__ float g_HsT[2][H*NN];      // src-side attention proj, DIM-MAJOR [j][s], double buffered
__device__ float g_Av [2][NN*H];      // src-side value proj (+val_b1), row-major, double buffered
__device__ float g_eaT[ED*EE];        // edge_attr transposed: eaT[k][d][s]

__device__ __forceinline__ float warp_sum(float v) {
#pragma unroll
    for (int o = 16; o; o >>= 1) v += __shfl_xor_sync(0xffffffffu, v, o);
    return v;
}
__device__ __forceinline__ float warp_max(float v) {
#pragma unroll
    for (int o = 16; o; o >>= 1) v = fmaxf(v, __shfl_xor_sync(0xffffffffu, v, o));
    return v;
}

// Packed fp32x2 ops (sm_103a): 2 fp32 FMAs per instruction
__device__ __forceinline__ float2 ffma2(float2 a, float2 b, float2 c) {
    unsigned long long ua, ub, uc, ur;
    memcpy(&ua, &a, 8); memcpy(&ub, &b, 8); memcpy(&uc, &c, 8);
    asm("fma.rn.f32x2 %0, %1, %2, %3;" : "=l"(ur) : "l"(ua), "l"(ub), "l"(uc));
    float2 r; memcpy(&r, &ur, 8); return r;
}
__device__ __forceinline__ float2 fadd2(float2 a, float2 b) {
    unsigned long long ua, ub, ur;
    memcpy(&ua, &a, 8); memcpy(&ub, &b, 8);
    asm("add.rn.f32x2 %0, %1, %2;" : "=l"(ur) : "l"(ua), "l"(ub));
    float2 r; memcpy(&r, &ur, 8); return r;
}
__device__ __forceinline__ float2 fmul2(float2 a, float2 b) {
    unsigned long long ua, ub, ur;
    memcpy(&ua, &a, 8); memcpy(&ub, &b, 8);
    asm("mul.rn.f32x2 %0, %1, %2;" : "=l"(ur) : "l"(ua), "l"(ub));
    float2 r; memcpy(&r, &ur, 8); return r;
}
__device__ __forceinline__ float2 dup2(float v) { return make_float2(v, v); }

// Per-node tables: Hd = h@Wa[0:64]+b1a (row), HsT = h@Wa[64:128] (dim-major), Av = h@Wv[0:64]+b1v (row)
__device__ __forceinline__ void compute_tables(
    int d, int t, int wb, const float* h_sh,
    const float* __restrict__ attW1, const float* __restrict__ attB1,
    const float* __restrict__ valW1, const float* __restrict__ valB1)
{
    float ad = attB1[t], as = 0.f, av = valB1[t];
#pragma unroll 8
    for (int k = 0; k < H; k++) {
        float hk = h_sh[k];
        ad += hk * attW1[k * H + t];
        as += hk * attW1[(H + k) * H + t];
        av += hk * valW1[k * H + t];
    }
    g_Hd[d * H + t]       = ad;
    g_HsT[wb][t * NN + d] = as;
    g_Av[wb][d * H + t]   = av;
}

// Transpose edge_attr: ea[s][d][k] -> eaT[k][d][s]. grid (16,16), block 256.
__global__ void __launch_bounds__(256) ea_transpose_kernel(const float* __restrict__ ea)
{
    __shared__ float t_sh[ED][32][33];
    const int t = threadIdx.x, w = t >> 5, lane = t & 31;
    const int bs = blockIdx.x * 32, bd = blockIdx.y * 32;

#pragma unroll
    for (int rr = 0; rr < 4; rr++) {
        int s_loc = w + rr * 8;
        const float* base = ea + ((size_t)(bs + s_loc) * NN + bd) * ED + lane * ED;
        float2 v0 = *(const float2*)(base);
        float2 v1 = *(const float2*)(base + 2);
        float2 v2 = *(const float2*)(base + 4);
        t_sh[0][lane][s_loc] = v0.x; t_sh[1][lane][s_loc] = v0.y;
        t_sh[2][lane][s_loc] = v1.x; t_sh[3][lane][s_loc] = v1.y;
        t_sh[4][lane][s_loc] = v2.x; t_sh[5][lane][s_loc] = v2.y;
    }
    __syncthreads();
#pragma unroll
    for (int idx = t; idx < ED * 32 * 32; idx += 256) {
        int k = idx >> 10, r = idx & 1023, dl = r >> 5, sl = r & 31;
        g_eaT[(size_t)k * EE + (size_t)(bd + dl) * NN + bs + sl] = t_sh[k][dl][sl];
    }
}

// Encoder: h = relu(x@W1+b1)@W2+b2, then layer-0 tables (buffer 0). grid=512, block=64
__global__ void __launch_bounds__(H) enc_kernel(
    const float* __restrict__ x,
    const float* __restrict__ ew1, const float* __restrict__ eb1,
    const float* __restrict__ ew2, const float* __restrict__ eb2,
    const float* __restrict__ attW1, const float* __restrict__ attB1,
    const float* __restrict__ valW1, const float* __restrict__ valB1)
{
    int d = blockIdx.x, t = threadIdx.x;
    __shared__ float xs[ED], hid[H], hsn[H];
    if (t < ED) xs[t] = x[d * ED + t];
    __syncthreads();
    float a = eb1[t];
#pragma unroll
    for (int k = 0; k < ED; k++) a += xs[k] * ew1[k * H + t];
    hid[t] = fmaxf(a, 0.f);
    __syncthreads();
    float hv = eb2[t];
#pragma unroll 8
    for (int k = 0; k < H; k++) hv += hid[k] * ew2[k * H + t];
    g_h[d * H + t] = hv;
    hsn[t] = hv;
    __syncthreads();
    compute_tables(d, t, 0, hsn, attW1, attB1, valW1, valB1);
}

// Fused layer: one block per dst node d. 128 threads = 4 warps — small blocks so
// ALL 512 blocks are co-resident (≤4/SM needed, 6/SM allowed): single wave.
// Warp w owns srcs [w*128, w*128+128); lane owns 4 srcs (two f32x2 pairs),
// full j-loop 0..63. Per-warp register softmax over 128 srcs. Pass 2: warp w
// same srcs, dims (2*lane, 2*lane+1). Node MLP + LN + next tables fused.
__global__ void __launch_bounds__(128, 6) layer_kernel(
    const float* __restrict__ attW1e,   // [6,64] edge rows of att_w1[l]
    const float* __restrict__ attW2,    // [64]
    const float* __restrict__ valW1e,   // [6,64] edge rows of val_w1[l]
    const float* __restrict__ valW2, const float* __restrict__ valB2,
    const float* __restrict__ updW1, const float* __restrict__ updB1,
    const float* __restrict__ updW2, const float* __restrict__ updB2,
    const float* __restrict__ lng, const float* __restrict__ lnb,
    const float* __restrict__ nattW1, const float* __restrict__ nattB1,
    const float* __restrict__ nvalW1, const float* __restrict__ nvalB1,
    const float* __restrict__ decW1, const float* __restrict__ decB1,
    const float* __restrict__ decW2, const float* __restrict__ decB2,
    float* __restrict__ out, int rb, int last)
{
    const int d = blockIdx.x;
    const int t = threadIdx.x, w = t >> 5, lane = t & 31;
    const int wb = rb ^ 1;

    __shared__ float4 waA[H];        // per j: (wa0,wa1,wa2,wa3)
    __shared__ float4 waB[H];        // per j: (wa4,wa5,w2,hd)
    __shared__ float4 eaA[NN];       // per s: (e0,e1,e2,e3)
    __shared__ float2 eaB[NN];       // per s: (e4,e5)
    __shared__ float  wexp[NN];      // softmax weights
    __shared__ float  pm[4], ps[4], pacc[4 * H];
    __shared__ float  part2[2 * H], agg_sh[H], h_sh[H], tmp_sh[H], hid_sh[H], hn_sh[H], red_sh[4];

    // Prologue: weight table (non-duplicated) + Hd row
    if (t < H) {
        int j = t;
        waA[j] = make_float4(attW1e[0 * H + j], attW1e[1 * H + j],
                             attW1e[2 * H + j], attW1e[3 * H + j]);
        waB[j] = make_float4(attW1e[4 * H + j], attW1e[5 * H + j],
                             attW2[j], g_Hd[d * H + j]);
    }

    const float* HsT = g_HsT[rb];
    const float* AvL = g_Av[rb];
    const int sa = w * 128 + 4 * lane;   // 4 srcs: sa..sa+3

    // Load ea for the 4 srcs (float4 from eaT, contiguous) — registers
    float4 eaq[ED];
#pragma unroll
    for (int k = 0; k < ED; k++)
        eaq[k] = *(const float4*)(g_eaT + (size_t)k * EE + d * NN + sa);

    // Publish packed (non-duplicated) ea for pass 2 (each warp owns its srcs)
#pragma unroll
    for (int u = 0; u < 4; u++) {
        float e0 = (u == 0) ? eaq[0].x : (u == 1) ? eaq[0].y : (u == 2) ? eaq[0].z : eaq[0].w;
        float e1 = (u == 0) ? eaq[1].x : (u == 1) ? eaq[1].y : (u == 2) ? eaq[1].z : eaq[1].w;
        float e2 = (u == 0) ? eaq[2].x : (u == 1) ? eaq[2].y : (u == 2) ? eaq[2].z : eaq[2].w;
        float e3 = (u == 0) ? eaq[3].x : (u == 1) ? eaq[3].y : (u == 2) ? eaq[3].z : eaq[3].w;
        float e4 = (u == 0) ? eaq[4].x : (u == 1) ? eaq[4].y : (u == 2) ? eaq[4].z : eaq[4].w;
        float e5 = (u == 0) ? eaq[5].x : (u == 1) ? eaq[5].y : (u == 2) ? eaq[5].z : eaq[5].w;
        eaA[sa + u] = make_float4(e0, e1, e2, e3);
        eaB[sa + u] = make_float2(e4, e5);
    }

    // Src pairs for f32x2: A = (sa, sa+1), B = (sa+2, sa+3)
    float2 eA[ED], eB[ED];
#pragma unroll
    for (int k = 0; k < ED; k++) {
        eA[k] = make_float2(eaq[k].x, eaq[k].y);
        eB[k] = make_float2(eaq[k].z, eaq[k].w);
    }
    __syncthreads();

    // ---- Pass 1: attention logits, full j-loop ----
    float2 lgA = make_float2(0.f, 0.f), lgB = make_float2(0.f, 0.f);
#pragma unroll 8
    for (int j = 0; j < H; j++) {
        float4 wAv = waA[j];
        float4 wBv = waB[j];
        float4 hs4 = *(const float4*)(HsT + j * NN + sa);
        float2 W0 = dup2(wAv.x), W1 = dup2(wAv.y), W2 = dup2(wAv.z), W3 = dup2(wAv.w);
        float2 W4 = dup2(wBv.x), W5 = dup2(wBv.y), Wo = dup2(wBv.z), HD = dup2(wBv.w);
        // split z into two 3-deep chains per src pair (4 independent chains)
        float2 zA  = fadd2(make_float2(hs4.x, hs4.y), HD);
        float2 zB  = fadd2(make_float2(hs4.z, hs4.w), HD);
        float2 zA2 = fmul2(eA[3], W3);
        float2 zB2 = fmul2(eB[3], W3);
        zA  = ffma2(eA[0], W0, zA);   zB  = ffma2(eB[0], W0, zB);
        zA2 = ffma2(eA[4], W4, zA2);  zB2 = ffma2(eB[4], W4, zB2);
        zA  = ffma2(eA[1], W1, zA);   zB  = ffma2(eB[1], W1, zB);
        zA2 = ffma2(eA[5], W5, zA2);  zB2 = ffma2(eB[5], W5, zB2);
        zA  = ffma2(eA[2], W2, zA);   zB  = ffma2(eB[2], W2, zB);
        zA  = fadd2(zA, zA2);         zB  = fadd2(zB, zB2);
        // leaky_relu(., 0.2)
        float2 sA = fmul2(zA, make_float2(0.2f, 0.2f));
        float2 sB = fmul2(zB, make_float2(0.2f, 0.2f));
        zA.x = fmaxf(zA.x, sA.x); zA.y = fmaxf(zA.y, sA.y);
        zB.x = fmaxf(zB.x, sB.x); zB.y = fmaxf(zB.y, sB.y);
        lgA = ffma2(zA, Wo, lgA);
        lgB = ffma2(zB, Wo, lgB);
    }

    // ---- Per-warp register softmax over this warp's 128 srcs ----
    {
        float m = warp_max(fmaxf(fmaxf(lgA.x, lgA.y), fmaxf(lgB.x, lgB.y)));
        float e0 = __expf(lgA.x - m), e1 = __expf(lgA.y - m);
        float e2 = __expf(lgB.x - m), e3 = __expf(lgB.y - m);
        float s_w = warp_sum(e0 + e1 + e2 + e3);
        if (lane == 0) { pm[w] = m; ps[w] = s_w; }
        *(float4*)(wexp + sa) = make_float4(e0, e1, e2, e3);
    }
    __syncthreads();

    // ---- Pass 2: alpha-weighted value aggregation (f32x2, 2 dims/lane) ----
    const int j0 = 2 * lane;
    float2 wv[ED];
#pragma unroll
    for (int k = 0; k < ED; k++) wv[k] = *(const float2*)(valW1e + k * H + j0);

    float2 acc0 = make_float2(0.f, 0.f), acc1 = make_float2(0.f, 0.f);
    const int s0 = w * 128;
#pragma unroll 4
    for (int i = 0; i < 128; i += 4) {
        float4 wg4 = *(const float4*)(wexp + s0 + i);
#pragma unroll
        for (int u = 0; u < 4; u++) {
            int s = s0 + i + u;
            float4 dA = eaA[s];
            float2 dB = eaB[s];
            float2 p = *(const float2*)(AvL + s * H + j0);
            p = ffma2(dup2(dA.x), wv[0], p);
            p = ffma2(dup2(dA.y), wv[1], p);
            p = ffma2(dup2(dA.z), wv[2], p);
            p = ffma2(dup2(dA.w), wv[3], p);
            p = ffma2(dup2(dB.x), wv[4], p);
            p = ffma2(dup2(dB.y), wv[5], p);
            p.x = fmaxf(p.x, 0.f);
            p.y = fmaxf(p.y, 0.f);
            float wt = (u == 0) ? wg4.x : (u == 1) ? wg4.y : (u == 2) ? wg4.z : wg4.w;
            if (u & 1) acc1 = ffma2(dup2(wt), p, acc1);
            else       acc0 = ffma2(dup2(wt), p, acc0);
        }
    }
    acc0 = fadd2(acc0, acc1);
    *(float2*)(pacc + w * H + j0) = acc0;
    __syncthreads();

    // ---- Combine 4 warp softmax partials ----
    if (t < H) {
        float M = fmaxf(fmaxf(pm[0], pm[1]), fmaxf(pm[2], pm[3]));
        float sc0 = __expf(pm[0] - M), sc1 = __expf(pm[1] - M);
        float sc2 = __expf(pm[2] - M), sc3 = __expf(pm[3] - M);
        float stot = ps[0] * sc0 + ps[1] * sc1 + ps[2] * sc2 + ps[3] * sc3;
        float a = pacc[0 * H + t] * sc0 + pacc[1 * H + t] * sc1
                + pacc[2 * H + t] * sc2 + pacc[3 * H + t] * sc3;
        agg_sh[t] = a / stot;
        h_sh[t]   = g_h[d * H + t];
    }
    __syncthreads();

    // ---- Node phase, 2-way k-split matvecs over 128 threads ----
    const int o = t & 63, q = t >> 6;

    // stage 1: tmp = val_b2 + agg @ val_w2
    {
        float p = 0.f;
        int k0 = q * 32;
#pragma unroll
        for (int kk = 0; kk < 32; kk++) p += agg_sh[k0 + kk] * valW2[(k0 + kk) * H + o];
        part2[q * H + o] = p;
    }
    __syncthreads();
    if (t < H) tmp_sh[t] = valB2[t] + part2[t] + part2[H + t];
    __syncthreads();

    // stage 2: hid = relu(upd_b1 + [h,tmp] @ upd_w1)
    {
        const float* srcv = (q == 0) ? h_sh : tmp_sh;
        int rbase = q * H;
        float p = 0.f;
#pragma unroll
        for (int kk = 0; kk < 64; kk++) p += srcv[kk] * updW1[(rbase + kk) * H + o];
        part2[q * H + o] = p;
    }
    __syncthreads();
    if (t < H) hid_sh[t] = fmaxf(updB1[t] + part2[t] + part2[H + t], 0.f);
    __syncthreads();

    // stage 3: u = upd_b2 + hid @ upd_w2
    {
        float p = 0.f;
        int k0 = q * 32;
#pragma unroll
        for (int kk = 0; kk < 32; kk++) p += hid_sh[k0 + kk] * updW2[(k0 + kk) * H + o];
        part2[q * H + o] = p;
    }
    __syncthreads();

    // residual + LayerNorm (threads 0..63 = warps 0,1; fused sum/sumsq)
    float r = 0.f, dr = 0.f;
    if (t < H) {
        float u = updB2[t] + part2[t] + part2[H + t];
        r = u + h_sh[t];
        float s1 = warp_sum(r);
        float s2 = warp_sum(r * r);
        if (lane == 0) { red_sh[w] = s1; red_sh[w + 2] = s2; }
    }
    __syncthreads();
    if (t < H) {
        float mu  = (red_sh[0] + red_sh[1]) * (1.0f / H);
        float ex2 = (red_sh[2] + red_sh[3]) * (1.0f / H);
        float var = ex2 - mu * mu;
        dr = r - mu;
        float hn = lng[t] * dr * rsqrtf(var + LN_EPS) + lnb[t];
        hn_sh[t] = hn;
        if (!last) g_h[d * H + t] = hn;
    }
    __syncthreads();

    if (!last) {
        if (t < H)
            compute_tables(d, t, wb, hn_sh, nattW1, nattB1, nvalW1, nvalB1);
    } else {
        if (t < H) {
            float dh = decB1[t];
#pragma unroll 8
            for (int k = 0; k < H; k++) dh += hn_sh[k] * decW1[k * H + t];
            dh = fmaxf(dh, 0.f);
            float p = dh * decW2[t];
            float psum = warp_sum(p);
            if (lane == 0) red_sh[w] = psum;
        }
        __syncthreads();
        if (t == 0) out[d] = red_sh[0] + red_sh[1] + decB2[0];
    }
}

extern "C" void kernel_launch(void* const* d_in, const int* in_sizes, int n_in,
                              void* d_out, int out_size)
{
    const float* x      = (const float*)d_in[0];
    const float* ea     = (const float*)d_in[1];
    const float* enc_w1 = (const float*)d_in[2];
    const float* enc_b1 = (const float*)d_in[3];
    const float* enc_w2 = (const float*)d_in[4];
    const float* enc_b2 = (const float*)d_in[5];
    const float* att_w1 = (const float*)d_in[6];   // [4,134,64]
    const float* att_b1 = (const float*)d_in[7];   // [4,64]
    const float* att_w2 = (const float*)d_in[8];   // [4,64,1]
    // d_in[9] = att_b2 — cancels inside softmax, unused
    const float* val_w1 = (const float*)d_in[10];  // [4,70,64]
    const float* val_b1 = (const float*)d_in[11];  // [4,64]
    const float* val_w2 = (const float*)d_in[12];  // [4,64,64]
    const float* val_b2 = (const float*)d_in[13];  // [4,64]
    const float* upd_w1 = (const float*)d_in[14];  // [4,128,64]
    const float* upd_b1 = (const float*)d_in[15];  // [4,64]
    const float* upd_w2 = (const float*)d_in[16];  // [4,64,64]
    const float* upd_b2 = (const float*)d_in[17];  // [4,64]
    const float* ln_g   = (const float*)d_in[18];  // [4,64]
    const float* ln_b   = (const float*)d_in[19];  // [4,64]
    const float* dec_w1 = (const float*)d_in[20];
    const float* dec_b1 = (const float*)d_in[21];
    const float* dec_w2 = (const float*)d_in[22];
    const float* dec_b2 = (const float*)d_in[23];
    // d_in[24] = edge_index: src=e/512, dst=e%512 (structure exploited directly)

    float* out = (float*)d_out;

    ea_transpose_kernel<<<dim3(16, 16), 256>>>(ea);
    enc_kernel<<<NN, H>>>(x, enc_w1, enc_b1, enc_w2, enc_b2,
                          att_w1, att_b1, val_w1, val_b1);

    for (int l = 0; l < NL; l++) {
        int last = (l == NL - 1);
        int nl = (l + 1) % NL;      // dummy-but-valid pointers on last layer
        int rb = l & 1;             // enc wrote buffer 0; layer l reads l&1, writes (l&1)^1
        layer_kernel<<<NN, 128>>>(att_w1 + (l * 134 + 128) * H,
                                  att_w2 + l * H,
                                  val_w1 + (l * 70 + 64) * H,
                                  val_w2 + l * H * H, val_b2 + l * H,
                                  upd_w1 + l * 2 * H * H, upd_b1 + l * H,
                                  upd_w2 + l * H * H, upd_b2 + l * H,
                                  ln_g + l * H, ln_b + l * H,
                                  att_w1 + nl * 134 * H, att_b1 + nl * H,
                                  val_w1 + nl * 70 * H, val_b1 + nl * H,
                                  dec_w1, dec_b1, dec_w2, dec_b2,
                                  out, rb, last);
    }
}